// round 3
// baseline (speedup 1.0000x reference)
#include <cuda_runtime.h>

typedef unsigned long long u64;

#define BATCH 4096
#define TT 48
#define FF 64
#define HH 128
#define NTH 256
#define RPB 32
#define NBLK (BATCH / RPB)   // 128
#define RS (TT * FF)         // 3072
#define IMP_N (BATCH * RS)   // 12582912

// ---------------- device scratch (no allocations allowed) ----------------
__device__ float g_Wg[256 * 512];   // gates weights, [k][col], col = 4*hu + gate
__device__ float g_bg[512];         // b_ih + b_hh in interleaved col order
__device__ float g_invden[TT];
__device__ float g_losspart[NBLK];

// ---------------- f32x2 helpers ----------------
__device__ __forceinline__ u64 f2pack(float a, float b) {
    u64 r; asm("mov.b64 %0,{%1,%2};" : "=l"(r) : "f"(a), "f"(b)); return r;
}
__device__ __forceinline__ u64 f2dup(float a) {
    u64 r; asm("mov.b64 %0,{%1,%1};" : "=l"(r) : "f"(a)); return r;
}
__device__ __forceinline__ void f2unpack(u64 v, float& a, float& b) {
    asm("mov.b64 {%0,%1},%2;" : "=f"(a), "=f"(b) : "l"(v));
}
__device__ __forceinline__ void f2fma(u64& d, u64 a, u64 b) {
    asm("fma.rn.f32x2 %0,%1,%2,%0;" : "+l"(d) : "l"(a), "l"(b));
}
__device__ __forceinline__ void ldgv2(const u64* p, u64& a, u64& b) {
    asm("ld.global.nc.v2.b64 {%0,%1},[%2];" : "=l"(a), "=l"(b) : "l"(p));
}
__device__ __forceinline__ float sigf(float x) {
    return __fdividef(1.f, 1.f + __expf(-x));
}
__device__ __forceinline__ float tanhf_(float x) {
    float e = __expf(2.f * x);
    return 1.f - __fdividef(2.f, e + 1.f);
}

// ---------------- shared memory layout (~195 KB) ----------------
struct SM {
    u64 wdh2[64][64];    // gamma_h W: [k=0..63][ju] = (Wdh[2ju][k], Wdh[2ju+1][k])
    u64 wh2[128][32];    // x_h W:     [k=0..127][ju] = (Wh[2ju][k], Wh[2ju+1][k])
    u64 wf2[64][32];     // z_h W (diag zeroed)
    u64 wc2[128][32];    // alpha W
    u64 bgs2[256];       // gate bias pairs (interleaved col order)
    float XI[256][33];   // k: 0..63 c_c | 64..127 m | 128..255 h   (scalar [k][row])
    float Cst[128][33];  // LSTM cell state
    float Xv[64][33];    // x values
    float Dl[64][33];    // deltas, then reused as x_c
    float GX[64][33];    // gamma_x
    float bdh[128];
    float bh[64]; float bf[64]; float bc[64]; float wdx[64]; float bdx[64];
    float wos[128];
    float red[8];
    float bo0;
};

// ---------------- prep 1: 1/denom per t ----------------
__global__ void k_denom(const float* __restrict__ masks) {
    __shared__ float buf[256];
    int t = blockIdx.x;
    float s = 0.f;
    for (int i = threadIdx.x; i < BATCH * FF; i += 256) {
        int b = i >> 6, f = i & 63;
        s += masks[b * RS + t * FF + f];
    }
    buf[threadIdx.x] = s;
    __syncthreads();
    for (int st = 128; st; st >>= 1) {
        if (threadIdx.x < st) buf[threadIdx.x] += buf[threadIdx.x + st];
        __syncthreads();
    }
    if (threadIdx.x == 0) g_invden[t] = 1.f / (buf[0] + 1e-5f);
}

// ---------------- prep 2: interleaved gate weights/bias ----------------
__global__ void k_prepw(const float* __restrict__ W_ih, const float* __restrict__ W_hh,
                        const float* __restrict__ b_ih, const float* __restrict__ b_hh) {
    int idx = blockIdx.x * 256 + threadIdx.x;   // 131072 total
    int c = idx & 511, k = idx >> 9;
    int gate = c & 3, hu = c >> 2;
    int j = gate * 128 + hu;                     // PyTorch gate-major row
    g_Wg[k * 512 + c] = (k < 128) ? W_ih[j * 128 + k] : W_hh[j * 128 + (k - 128)];
    if (idx < 512) g_bg[c] = b_ih[j] + b_hh[j];
}

// ---------------- finalize: deterministic loss sum ----------------
__global__ void k_fin(float* __restrict__ out) {
    if (threadIdx.x == 0) {
        float s = 0.f;
        for (int i = 0; i < NBLK; i++) s += g_losspart[i];
        out[0] = s;
    }
}

// ---------------- main persistent recurrent kernel ----------------
__global__ void __launch_bounds__(NTH, 1) brits_main(
    const float* __restrict__ values, const float* __restrict__ masks,
    const float* __restrict__ deltas,
    const float* __restrict__ Wdh, const float* __restrict__ bdh,
    const float* __restrict__ Wdx, const float* __restrict__ bdx,
    const float* __restrict__ Wh,  const float* __restrict__ bh,
    const float* __restrict__ Wf,  const float* __restrict__ bf,
    const float* __restrict__ Wc,  const float* __restrict__ bc,
    const float* __restrict__ Wo,  const float* __restrict__ bo,
    float* __restrict__ out)
{
    extern __shared__ char smraw[];
    SM& S = *reinterpret_cast<SM*>(smraw);
    const int tid = threadIdx.x;
    const int row0 = blockIdx.x * RPB;

    // ---- stage small weights (unit-pair packed, transposed) ----
    for (int i = tid; i < 64 * 64; i += NTH) {
        int k = i & 63, ju = i >> 6;
        S.wdh2[k][ju] = f2pack(Wdh[(2 * ju) * 64 + k], Wdh[(2 * ju + 1) * 64 + k]);
    }
    for (int i = tid; i < 128 * 32; i += NTH) {
        int ju = i & 31, k = i >> 5;
        S.wh2[k][ju] = f2pack(Wh[(2 * ju) * 128 + k], Wh[(2 * ju + 1) * 128 + k]);
    }
    for (int i = tid; i < 64 * 32; i += NTH) {
        int ju = i & 31, k = i >> 5;
        float a = (2 * ju == k) ? 0.f : Wf[(2 * ju) * 64 + k];
        float b = (2 * ju + 1 == k) ? 0.f : Wf[(2 * ju + 1) * 64 + k];
        S.wf2[k][ju] = f2pack(a, b);
    }
    for (int i = tid; i < 128 * 32; i += NTH) {
        int ju = i & 31, k = i >> 5;
        S.wc2[k][ju] = f2pack(Wc[(2 * ju) * 128 + k], Wc[(2 * ju + 1) * 128 + k]);
    }
    for (int i = tid; i < 256; i += NTH)
        S.bgs2[i] = f2pack(g_bg[2 * i], g_bg[2 * i + 1]);
    if (tid < 128) { S.bdh[tid] = bdh[tid]; S.wos[tid] = Wo[tid]; }
    if (tid < 64) {
        S.bh[tid] = bh[tid]; S.bf[tid] = bf[tid]; S.bc[tid] = bc[tid];
        S.wdx[tid] = Wdx[tid * 64 + tid]; S.bdx[tid] = bdx[tid];
    }
    if (tid == 0) S.bo0 = bo[0];
    // zero h and c
    for (int i = tid; i < 128 * 33; i += NTH) {
        S.Cst[i / 33][i % 33] = 0.f;
        S.XI[128 + i / 33][i % 33] = 0.f;
    }
    __syncthreads();

    const int rg1 = tid & 7, ug1 = tid >> 3;   // p1: rows 4*rg1.., units 4*ug1..
    const int rg2 = tid & 7, fg2 = tid >> 3;   // p2/p3: rows 4*rg2.., f = 2*fg2..
    const int rg4 = tid & 3, cg4 = tid >> 2;   // p4: rows 8*rg4.., cols 8*cg4..
    float loss_acc = 0.f;
    float* outImp = out + 1;

    for (int t = 0; t < TT; ++t) {
        // ---- p0: load x, m, d (coalesced) ----
        for (int i = tid; i < RPB * FF; i += NTH) {
            int r = i >> 6, f = i & 63;
            int g = (row0 + r) * RS + t * FF + f;
            S.Xv[f][r] = values[g];
            S.XI[64 + f][r] = masks[g];
            S.Dl[f][r] = deltas[g];
        }
        __syncthreads();

        // ---- p1: gamma_h GEMM (k=64) -> h *= gh ; gamma_x elementwise ----
        {
            u64 acc[4][2];
            u64 b0 = f2pack(S.bdh[4 * ug1],     S.bdh[4 * ug1 + 1]);
            u64 b1 = f2pack(S.bdh[4 * ug1 + 2], S.bdh[4 * ug1 + 3]);
            #pragma unroll
            for (int rr = 0; rr < 4; rr++) { acc[rr][0] = b0; acc[rr][1] = b1; }
            #pragma unroll 4
            for (int k = 0; k < 64; k++) {
                u64 w0 = S.wdh2[k][2 * ug1], w1 = S.wdh2[k][2 * ug1 + 1];
                #pragma unroll
                for (int rr = 0; rr < 4; rr++) {
                    u64 a = f2dup(S.Dl[k][4 * rg1 + rr]);
                    f2fma(acc[rr][0], a, w0);
                    f2fma(acc[rr][1], a, w1);
                }
            }
            #pragma unroll
            for (int rr = 0; rr < 4; rr++) {
                int row = 4 * rg1 + rr;
                #pragma unroll
                for (int j = 0; j < 2; j++) {
                    float z0, z1; f2unpack(acc[rr][j], z0, z1);
                    int u = 4 * ug1 + 2 * j;
                    S.XI[128 + u][row]     *= __expf(-fmaxf(z0, 0.f));
                    S.XI[128 + u + 1][row] *= __expf(-fmaxf(z1, 0.f));
                }
            }
            for (int i = tid; i < RPB * FF; i += NTH) {
                int r = i >> 6, f = i & 63;
                float z = S.Dl[f][r] * S.wdx[f] + S.bdx[f];
                S.GX[f][r] = __expf(-fmaxf(z, 0.f));
            }
        }
        __syncthreads();

        // ---- p2: x_h GEMM (k=128) + loss1 + x_c -> Dl ----
        float xh_r[4][2];
        float s_loss = 0.f;
        {
            u64 acc[4];
            u64 binit = f2pack(S.bh[2 * fg2], S.bh[2 * fg2 + 1]);
            #pragma unroll
            for (int rr = 0; rr < 4; rr++) acc[rr] = binit;
            #pragma unroll 4
            for (int k = 0; k < 128; k++) {
                u64 w = S.wh2[k][fg2];
                #pragma unroll
                for (int rr = 0; rr < 4; rr++) {
                    u64 a = f2dup(S.XI[128 + k][4 * rg2 + rr]);
                    f2fma(acc[rr], a, w);
                }
            }
            #pragma unroll
            for (int rr = 0; rr < 4; rr++) {
                int row = 4 * rg2 + rr;
                f2unpack(acc[rr], xh_r[rr][0], xh_r[rr][1]);
                #pragma unroll
                for (int s = 0; s < 2; s++) {
                    int f = 2 * fg2 + s;
                    float x = S.Xv[f][row], m = S.XI[64 + f][row];
                    float xh = xh_r[rr][s];
                    s_loss += fabsf(x - xh) * m;
                    S.Dl[f][row] = m * x + (1.f - m) * xh;
                }
            }
        }
        __syncthreads();

        // ---- p3: z_h GEMM (k=64) + alpha GEMM (k=128) + c_h/c_c + losses ----
        {
            u64 az[4], aa[4];
            u64 bz = f2pack(S.bf[2 * fg2], S.bf[2 * fg2 + 1]);
            u64 ba = f2pack(S.bc[2 * fg2], S.bc[2 * fg2 + 1]);
            #pragma unroll
            for (int rr = 0; rr < 4; rr++) { az[rr] = bz; aa[rr] = ba; }
            #pragma unroll 2
            for (int k = 0; k < 64; k++) {
                u64 wz = S.wf2[k][fg2], wa = S.wc2[k][fg2];
                #pragma unroll
                for (int rr = 0; rr < 4; rr++) {
                    int row = 4 * rg2 + rr;
                    u64 axc = f2dup(S.Dl[k][row]); f2fma(az[rr], axc, wz);
                    u64 agx = f2dup(S.GX[k][row]); f2fma(aa[rr], agx, wa);
                }
            }
            #pragma unroll 2
            for (int k = 64; k < 128; k++) {
                u64 wa = S.wc2[k][fg2];
                #pragma unroll
                for (int rr = 0; rr < 4; rr++) {
                    u64 am = f2dup(S.XI[k][4 * rg2 + rr]);   // m region
                    f2fma(aa[rr], am, wa);
                }
            }
            #pragma unroll
            for (int rr = 0; rr < 4; rr++) {
                int row = 4 * rg2 + rr;
                float zh0, zh1, al0, al1;
                f2unpack(az[rr], zh0, zh1);
                f2unpack(aa[rr], al0, al1);
                #pragma unroll
                for (int s = 0; s < 2; s++) {
                    int f = 2 * fg2 + s;
                    float zh = s ? zh1 : zh0, al = s ? al1 : al0;
                    float x = S.Xv[f][row], m = S.XI[64 + f][row];
                    float xh = xh_r[rr][s];
                    float ch = al * zh + (1.f - al) * xh;
                    s_loss += (fabsf(x - zh) + fabsf(x - ch)) * m;
                    float cc = m * x + (1.f - m) * ch;
                    outImp[(row0 + row) * RS + t * FF + f] = cc;
                    S.XI[f][row] = cc;
                }
            }
            loss_acc += s_loss * g_invden[t];
        }
        __syncthreads();

        // ---- p4: gates GEMM (k=256) + LSTM update ----
        {
            u64 acc[8][4];
            #pragma unroll
            for (int rr = 0; rr < 8; rr++) {
                #pragma unroll
                for (int j = 0; j < 4; j++) acc[rr][j] = S.bgs2[4 * cg4 + j];
            }
            const u64* wp = reinterpret_cast<const u64*>(g_Wg) + cg4 * 4;
            #pragma unroll 2
            for (int k = 0; k < 256; k++) {
                u64 w0, w1, w2, w3;
                ldgv2(wp + (size_t)k * 256,     w0, w1);
                ldgv2(wp + (size_t)k * 256 + 2, w2, w3);
                #pragma unroll
                for (int rr = 0; rr < 8; rr++) {
                    u64 a = f2dup(S.XI[k][8 * rg4 + rr]);
                    f2fma(acc[rr][0], a, w0);
                    f2fma(acc[rr][1], a, w1);
                    f2fma(acc[rr][2], a, w2);
                    f2fma(acc[rr][3], a, w3);
                }
            }
            __syncthreads();   // all XI reads done before h writeback
            #pragma unroll
            for (int rr = 0; rr < 8; rr++) {
                int row = 8 * rg4 + rr;
                #pragma unroll
                for (int j2 = 0; j2 < 2; j2++) {
                    int hu = 2 * cg4 + j2;
                    float iv, fv, gv, ov;
                    f2unpack(acc[rr][2 * j2],     iv, fv);
                    f2unpack(acc[rr][2 * j2 + 1], gv, ov);
                    float co = S.Cst[hu][row];
                    float cn = sigf(fv) * co + sigf(iv) * tanhf_(gv);
                    float hn = sigf(ov) * tanhf_(cn);
                    S.Cst[hu][row] = cn;
                    S.XI[128 + hu][row] = hn;
                }
            }
        }
        __syncthreads();
    }

    // ---- loss block-reduce (deterministic per block) ----
    float v = loss_acc;
    #pragma unroll
    for (int o = 16; o; o >>= 1) v += __shfl_down_sync(0xffffffffu, v, o);
    if ((tid & 31) == 0) S.red[tid >> 5] = v;
    __syncthreads();
    if (tid == 0) {
        float s = 0.f;
        for (int w = 0; w < 8; w++) s += S.red[w];
        g_losspart[blockIdx.x] = s;
    }

    // ---- predictions: out[1 + IMP_N + b] = h @ Wo.T + bo ----
    if (tid < RPB) {
        float p = S.bo0;
        #pragma unroll 4
        for (int u = 0; u < 128; u++) p += S.XI[128 + u][tid] * S.wos[u];
        out[1 + IMP_N + row0 + tid] = p;
    }
}

extern "C" void kernel_launch(void* const* d_in, const int* in_sizes, int n_in,
                              void* d_out, int out_size) {
    const float* values = (const float*)d_in[0];
    const float* masks  = (const float*)d_in[1];
    const float* deltas = (const float*)d_in[2];
    const float* Wdh = (const float*)d_in[3];
    const float* bdh = (const float*)d_in[4];
    const float* Wdx = (const float*)d_in[5];
    const float* bdx = (const float*)d_in[6];
    const float* Wh  = (const float*)d_in[7];
    const float* bh  = (const float*)d_in[8];
    const float* Wf  = (const float*)d_in[9];
    const float* bf  = (const float*)d_in[10];
    const float* Wc  = (const float*)d_in[11];
    const float* bc  = (const float*)d_in[12];
    const float* W_ih = (const float*)d_in[13];
    const float* W_hh = (const float*)d_in[14];
    const float* b_ih = (const float*)d_in[15];
    const float* b_hh = (const float*)d_in[16];
    const float* Wo  = (const float*)d_in[17];
    const float* bo  = (const float*)d_in[18];
    float* out = (float*)d_out;

    cudaFuncSetAttribute(brits_main, cudaFuncAttributeMaxDynamicSharedMemorySize,
                         (int)sizeof(SM));

    k_denom<<<TT, 256>>>(masks);
    k_prepw<<<512, 256>>>(W_ih, W_hh, b_ih, b_hh);
    brits_main<<<NBLK, NTH, sizeof(SM)>>>(values, masks, deltas,
                                          Wdh, bdh, Wdx, bdx, Wh, bh, Wf, bf,
                                          Wc, bc, Wo, bo, out);
    k_fin<<<1, 32>>>(out);
}

// round 4
// speedup vs baseline: 1.3549x; 1.3549x over previous
#include <cuda_runtime.h>

typedef unsigned long long u64;

#define BATCH 4096
#define TT 48
#define FF 64
#define HH 128
#define NTH 256
#define RPB 32
#define NBLK (BATCH / RPB)   // 128
#define RS (TT * FF)         // 3072
#define IMP_N (BATCH * RS)   // 12582912

// ---------------- device scratch (no allocations allowed) ----------------
__device__ float g_Wg[256 * 512];   // gates weights, [k][col], col = 4*hu + gate
__device__ float g_bg[512];         // b_ih + b_hh in interleaved col order
__device__ float g_invden[TT];
__device__ float g_losspart[NBLK];

// ---------------- f32x2 helpers ----------------
__device__ __forceinline__ u64 f2pack(float a, float b) {
    u64 r; asm("mov.b64 %0,{%1,%2};" : "=l"(r) : "f"(a), "f"(b)); return r;
}
__device__ __forceinline__ u64 f2dup(float a) {
    u64 r; asm("mov.b64 %0,{%1,%1};" : "=l"(r) : "f"(a)); return r;
}
__device__ __forceinline__ void f2unpack(u64 v, float& a, float& b) {
    asm("mov.b64 {%0,%1},%2;" : "=f"(a), "=f"(b) : "l"(v));
}
__device__ __forceinline__ void f2fma(u64& d, u64 a, u64 b) {
    asm("fma.rn.f32x2 %0,%1,%2,%0;" : "+l"(d) : "l"(a), "l"(b));
}
__device__ __forceinline__ void ldgv2(const u64* p, u64& a, u64& b) {
    asm("ld.global.nc.v2.b64 {%0,%1},[%2];" : "=l"(a), "=l"(b) : "l"(p));
}
__device__ __forceinline__ float sigf(float x) {
    return __fdividef(1.f, 1.f + __expf(-x));
}
__device__ __forceinline__ float tanhf_(float x) {
    float e = __expf(2.f * x);
    return 1.f - __fdividef(2.f, e + 1.f);
}

// ---------------- shared memory layout (~197 KB) ----------------
// All activation arrays use stride 34 (even -> float2-aligned paired loads).
struct SM {
    u64 wdh2[64][64];    // gamma_h W: [k][ju] = (Wdh[2ju][k], Wdh[2ju+1][k])
    u64 wh2[128][32];    // x_h W
    u64 wf2[64][32];     // z_h W (diag zeroed)
    u64 wc2[128][32];    // alpha W
    u64 bgs2[256];       // gate bias pairs (interleaved col order)
    float XI[256][34];   // k: 0..63 c_c | 64..127 m | 128..255 h
    float Cst[128][34];  // LSTM cell state
    float Xv[64][34];    // x values
    float Dl[64][34];    // deltas, then reused as x_c
    float GX[64][34];    // gamma_x
    float bdh[128];
    float bh[64]; float bf[64]; float bc[64]; float wdx[64]; float bdx[64];
    float wos[128];
    float red[8];
    float bo0;
};

// ---------------- prep 1: 1/denom per t ----------------
__global__ void k_denom(const float* __restrict__ masks) {
    __shared__ float buf[256];
    int t = blockIdx.x;
    float s = 0.f;
    for (int i = threadIdx.x; i < BATCH * FF; i += 256) {
        int b = i >> 6, f = i & 63;
        s += masks[b * RS + t * FF + f];
    }
    buf[threadIdx.x] = s;
    __syncthreads();
    for (int st = 128; st; st >>= 1) {
        if (threadIdx.x < st) buf[threadIdx.x] += buf[threadIdx.x + st];
        __syncthreads();
    }
    if (threadIdx.x == 0) g_invden[t] = 1.f / (buf[0] + 1e-5f);
}

// ---------------- prep 2: interleaved gate weights/bias ----------------
__global__ void k_prepw(const float* __restrict__ W_ih, const float* __restrict__ W_hh,
                        const float* __restrict__ b_ih, const float* __restrict__ b_hh) {
    int idx = blockIdx.x * 256 + threadIdx.x;   // 131072 total
    int c = idx & 511, k = idx >> 9;
    int gate = c & 3, hu = c >> 2;
    int j = gate * 128 + hu;                     // PyTorch gate-major row
    g_Wg[k * 512 + c] = (k < 128) ? W_ih[j * 128 + k] : W_hh[j * 128 + (k - 128)];
    if (idx < 512) g_bg[c] = b_ih[j] + b_hh[j];
}

// ---------------- finalize: deterministic loss sum ----------------
__global__ void k_fin(float* __restrict__ out) {
    if (threadIdx.x == 0) {
        float s = 0.f;
        for (int i = 0; i < NBLK; i++) s += g_losspart[i];
        out[0] = s;
    }
}

// ---------------- main persistent recurrent kernel ----------------
__global__ void __launch_bounds__(NTH, 1) brits_main(
    const float* __restrict__ values, const float* __restrict__ masks,
    const float* __restrict__ deltas,
    const float* __restrict__ Wdh, const float* __restrict__ bdh,
    const float* __restrict__ Wdx, const float* __restrict__ bdx,
    const float* __restrict__ Wh,  const float* __restrict__ bh,
    const float* __restrict__ Wf,  const float* __restrict__ bf,
    const float* __restrict__ Wc,  const float* __restrict__ bc,
    const float* __restrict__ Wo,  const float* __restrict__ bo,
    float* __restrict__ out)
{
    extern __shared__ char smraw[];
    SM& S = *reinterpret_cast<SM*>(smraw);
    const int tid = threadIdx.x;
    const int row0 = blockIdx.x * RPB;

    // ---- stage small weights (unit-pair packed, transposed) ----
    for (int i = tid; i < 64 * 64; i += NTH) {
        int k = i & 63, ju = i >> 6;
        S.wdh2[k][ju] = f2pack(Wdh[(2 * ju) * 64 + k], Wdh[(2 * ju + 1) * 64 + k]);
    }
    for (int i = tid; i < 128 * 32; i += NTH) {
        int ju = i & 31, k = i >> 5;
        S.wh2[k][ju] = f2pack(Wh[(2 * ju) * 128 + k], Wh[(2 * ju + 1) * 128 + k]);
    }
    for (int i = tid; i < 64 * 32; i += NTH) {
        int ju = i & 31, k = i >> 5;
        float a = (2 * ju == k) ? 0.f : Wf[(2 * ju) * 64 + k];
        float b = (2 * ju + 1 == k) ? 0.f : Wf[(2 * ju + 1) * 64 + k];
        S.wf2[k][ju] = f2pack(a, b);
    }
    for (int i = tid; i < 128 * 32; i += NTH) {
        int ju = i & 31, k = i >> 5;
        S.wc2[k][ju] = f2pack(Wc[(2 * ju) * 128 + k], Wc[(2 * ju + 1) * 128 + k]);
    }
    for (int i = tid; i < 256; i += NTH)
        S.bgs2[i] = f2pack(g_bg[2 * i], g_bg[2 * i + 1]);
    if (tid < 128) { S.bdh[tid] = bdh[tid]; S.wos[tid] = Wo[tid]; }
    if (tid < 64) {
        S.bh[tid] = bh[tid]; S.bf[tid] = bf[tid]; S.bc[tid] = bc[tid];
        S.wdx[tid] = Wdx[tid * 64 + tid]; S.bdx[tid] = bdx[tid];
    }
    if (tid == 0) S.bo0 = bo[0];
    // zero h and c
    for (int i = tid; i < 128 * 34; i += NTH) {
        S.Cst[i / 34][i % 34] = 0.f;
        S.XI[128 + i / 34][i % 34] = 0.f;
    }
    __syncthreads();

    // ---- prologue: load t=0 inputs + gamma_x ----
    #pragma unroll
    for (int j = 0; j < 8; j++) {
        int i = tid + j * NTH;
        int r = i >> 6, f = i & 63;
        int g = (row0 + r) * RS + 0 * FF + f;
        float x = values[g], m = masks[g], d = deltas[g];
        S.Xv[f][r] = x;
        S.XI[64 + f][r] = m;
        S.Dl[f][r] = d;
        S.GX[f][r] = __expf(-fmaxf(d * S.wdx[f] + S.bdx[f], 0.f));
    }
    __syncthreads();

    const int rg1 = tid & 7, ug1 = tid >> 3;   // p1: rows 4*rg1.., units 4*ug1..
    const int rg2 = tid & 7, fg2 = tid >> 3;   // p2/p3: rows 4*rg2.., f = 2*fg2..
    const int rg4 = tid & 3, cg4 = tid >> 2;   // p4: rows 8*rg4.., cols 8*cg4..
    float loss_acc = 0.f;
    float* outImp = out + 1;

    for (int t = 0; t < TT; ++t) {
        // ---- p1: gamma_h GEMM (k=64) -> h *= gh ----
        {
            u64 acc[4][2];
            u64 b0 = f2pack(S.bdh[4 * ug1],     S.bdh[4 * ug1 + 1]);
            u64 b1 = f2pack(S.bdh[4 * ug1 + 2], S.bdh[4 * ug1 + 3]);
            #pragma unroll
            for (int rr = 0; rr < 4; rr++) { acc[rr][0] = b0; acc[rr][1] = b1; }
            #pragma unroll 4
            for (int k = 0; k < 64; k++) {
                u64 w0 = S.wdh2[k][2 * ug1], w1 = S.wdh2[k][2 * ug1 + 1];
                #pragma unroll
                for (int h = 0; h < 2; h++) {
                    float2 ap = *(const float2*)&S.Dl[k][4 * rg1 + 2 * h];
                    u64 a0 = f2dup(ap.x), a1 = f2dup(ap.y);
                    f2fma(acc[2 * h][0], a0, w0);
                    f2fma(acc[2 * h][1], a0, w1);
                    f2fma(acc[2 * h + 1][0], a1, w0);
                    f2fma(acc[2 * h + 1][1], a1, w1);
                }
            }
            #pragma unroll
            for (int rr = 0; rr < 4; rr++) {
                int row = 4 * rg1 + rr;
                #pragma unroll
                for (int j = 0; j < 2; j++) {
                    float z0, z1; f2unpack(acc[rr][j], z0, z1);
                    int u = 4 * ug1 + 2 * j;
                    S.XI[128 + u][row]     *= __expf(-fmaxf(z0, 0.f));
                    S.XI[128 + u + 1][row] *= __expf(-fmaxf(z1, 0.f));
                }
            }
        }
        __syncthreads();

        // ---- p2: x_h GEMM (k=128) + loss1 + x_c -> Dl ----
        float xh_r[4][2];
        float s_loss = 0.f;
        {
            u64 acc[4];
            u64 binit = f2pack(S.bh[2 * fg2], S.bh[2 * fg2 + 1]);
            #pragma unroll
            for (int rr = 0; rr < 4; rr++) acc[rr] = binit;
            #pragma unroll 4
            for (int k = 0; k < 128; k++) {
                u64 w = S.wh2[k][fg2];
                #pragma unroll
                for (int h = 0; h < 2; h++) {
                    float2 ap = *(const float2*)&S.XI[128 + k][4 * rg2 + 2 * h];
                    f2fma(acc[2 * h],     f2dup(ap.x), w);
                    f2fma(acc[2 * h + 1], f2dup(ap.y), w);
                }
            }
            #pragma unroll
            for (int rr = 0; rr < 4; rr++) {
                int row = 4 * rg2 + rr;
                f2unpack(acc[rr], xh_r[rr][0], xh_r[rr][1]);
                #pragma unroll
                for (int s = 0; s < 2; s++) {
                    int f = 2 * fg2 + s;
                    float x = S.Xv[f][row], m = S.XI[64 + f][row];
                    float xh = xh_r[rr][s];
                    s_loss += fabsf(x - xh) * m;
                    S.Dl[f][row] = m * x + (1.f - m) * xh;
                }
            }
        }
        __syncthreads();

        // ---- p3: z_h GEMM (k=64) + alpha GEMM (k=128) + c_h/c_c + losses ----
        {
            u64 az[4], aa[4];
            u64 bz = f2pack(S.bf[2 * fg2], S.bf[2 * fg2 + 1]);
            u64 ba = f2pack(S.bc[2 * fg2], S.bc[2 * fg2 + 1]);
            #pragma unroll
            for (int rr = 0; rr < 4; rr++) { az[rr] = bz; aa[rr] = ba; }
            #pragma unroll 2
            for (int k = 0; k < 64; k++) {
                u64 wz = S.wf2[k][fg2], wa = S.wc2[k][fg2];
                #pragma unroll
                for (int rr = 0; rr < 4; rr++) {
                    int row = 4 * rg2 + rr;
                    u64 axc = f2dup(S.Dl[k][row]); f2fma(az[rr], axc, wz);
                    u64 agx = f2dup(S.GX[k][row]); f2fma(aa[rr], agx, wa);
                }
            }
            #pragma unroll 2
            for (int k = 64; k < 128; k++) {
                u64 wa = S.wc2[k][fg2];
                #pragma unroll
                for (int rr = 0; rr < 4; rr++) {
                    u64 am = f2dup(S.XI[k][4 * rg2 + rr]);   // m region
                    f2fma(aa[rr], am, wa);
                }
            }
            #pragma unroll
            for (int rr = 0; rr < 4; rr++) {
                int row = 4 * rg2 + rr;
                float zh0, zh1, al0, al1;
                f2unpack(az[rr], zh0, zh1);
                f2unpack(aa[rr], al0, al1);
                #pragma unroll
                for (int s = 0; s < 2; s++) {
                    int f = 2 * fg2 + s;
                    float zh = s ? zh1 : zh0, al = s ? al1 : al0;
                    float x = S.Xv[f][row], m = S.XI[64 + f][row];
                    float xh = xh_r[rr][s];
                    float ch = al * zh + (1.f - al) * xh;
                    s_loss += (fabsf(x - zh) + fabsf(x - ch)) * m;
                    S.XI[f][row] = m * x + (1.f - m) * ch;   // c_c
                }
            }
            loss_acc += s_loss * g_invden[t];
        }
        __syncthreads();

        // ---- p4: gates GEMM (k=256, 4-deep weight prefetch) + LSTM update ----
        {
            // prefetch next step's inputs during the GEMM (latency hidden)
            float px[8], pm[8], pd[8];
            const bool havenext = (t + 1 < TT);
            if (havenext) {
                #pragma unroll
                for (int j = 0; j < 8; j++) {
                    int i = tid + j * NTH;
                    int g = (row0 + (i >> 6)) * RS + (t + 1) * FF + (i & 63);
                    px[j] = values[g]; pm[j] = masks[g]; pd[j] = deltas[g];
                }
            }

            u64 w[4][4];
            const u64* wp = reinterpret_cast<const u64*>(g_Wg) + cg4 * 4;
            #pragma unroll
            for (int s = 0; s < 4; s++) {
                ldgv2(wp + (size_t)s * 256,     w[s][0], w[s][1]);
                ldgv2(wp + (size_t)s * 256 + 2, w[s][2], w[s][3]);
            }
            u64 acc[8][4];
            #pragma unroll
            for (int rr = 0; rr < 8; rr++) {
                #pragma unroll
                for (int j = 0; j < 4; j++) acc[rr][j] = S.bgs2[4 * cg4 + j];
            }
            #pragma unroll 4
            for (int k = 0; k < 256; k++) {
                const int s = k & 3;
                #pragma unroll
                for (int h = 0; h < 4; h++) {
                    float2 ap = *(const float2*)&S.XI[k][8 * rg4 + 2 * h];
                    u64 a0 = f2dup(ap.x), a1 = f2dup(ap.y);
                    #pragma unroll
                    for (int j = 0; j < 4; j++) {
                        f2fma(acc[2 * h][j],     a0, w[s][j]);
                        f2fma(acc[2 * h + 1][j], a1, w[s][j]);
                    }
                }
                if (k < 252) {
                    ldgv2(wp + (size_t)(k + 4) * 256,     w[s][0], w[s][1]);
                    ldgv2(wp + (size_t)(k + 4) * 256 + 2, w[s][2], w[s][3]);
                }
            }
            __syncthreads();   // all XI/mask reads done before writebacks

            // LSTM update (registers -> Cst, XI h-region)
            #pragma unroll
            for (int rr = 0; rr < 8; rr++) {
                int row = 8 * rg4 + rr;
                #pragma unroll
                for (int j2 = 0; j2 < 2; j2++) {
                    int hu = 2 * cg4 + j2;
                    float iv, fv, gv, ov;
                    f2unpack(acc[rr][2 * j2],     iv, fv);
                    f2unpack(acc[rr][2 * j2 + 1], gv, ov);
                    float co = S.Cst[hu][row];
                    float cn = sigf(fv) * co + sigf(iv) * tanhf_(gv);
                    float hn = sigf(ov) * tanhf_(cn);
                    S.Cst[hu][row] = cn;
                    S.XI[128 + hu][row] = hn;
                }
            }

            // coalesced imputation write (c_c from SMEM, row-contiguous)
            #pragma unroll
            for (int j = 0; j < 8; j++) {
                int i = tid + j * NTH;
                int r = i >> 6, f = i & 63;
                outImp[(row0 + r) * RS + t * FF + f] = S.XI[f][r];
            }

            // store prefetched next-step inputs + gamma_x
            if (havenext) {
                #pragma unroll
                for (int j = 0; j < 8; j++) {
                    int i = tid + j * NTH;
                    int r = i >> 6, f = i & 63;
                    S.Xv[f][r] = px[j];
                    S.XI[64 + f][r] = pm[j];
                    S.Dl[f][r] = pd[j];
                    S.GX[f][r] = __expf(-fmaxf(pd[j] * S.wdx[f] + S.bdx[f], 0.f));
                }
            }
        }
        __syncthreads();
    }

    // ---- loss block-reduce (deterministic per block) ----
    float v = loss_acc;
    #pragma unroll
    for (int o = 16; o; o >>= 1) v += __shfl_down_sync(0xffffffffu, v, o);
    if ((tid & 31) == 0) S.red[tid >> 5] = v;
    __syncthreads();
    if (tid == 0) {
        float s = 0.f;
        for (int w = 0; w < 8; w++) s += S.red[w];
        g_losspart[blockIdx.x] = s;
    }

    // ---- predictions: out[1 + IMP_N + b] = h @ Wo.T + bo ----
    if (tid < RPB) {
        float p = S.bo0;
        #pragma unroll 4
        for (int u = 0; u < 128; u++) p += S.XI[128 + u][tid] * S.wos[u];
        out[1 + IMP_N + row0 + tid] = p;
    }
}

extern "C" void kernel_launch(void* const* d_in, const int* in_sizes, int n_in,
                              void* d_out, int out_size) {
    const float* values = (const float*)d_in[0];
    const float* masks  = (const float*)d_in[1];
    const float* deltas = (const float*)d_in[2];
    const float* Wdh = (const float*)d_in[3];
    const float* bdh = (const float*)d_in[4];
    const float* Wdx = (const float*)d_in[5];
    const float* bdx = (const float*)d_in[6];
    const float* Wh  = (const float*)d_in[7];
    const float* bh  = (const float*)d_in[8];
    const float* Wf  = (const float*)d_in[9];
    const float* bf  = (const float*)d_in[10];
    const float* Wc  = (const float*)d_in[11];
    const float* bc  = (const float*)d_in[12];
    const float* W_ih = (const float*)d_in[13];
    const float* W_hh = (const float*)d_in[14];
    const float* b_ih = (const float*)d_in[15];
    const float* b_hh = (const float*)d_in[16];
    const float* Wo  = (const float*)d_in[17];
    const float* bo  = (const float*)d_in[18];
    float* out = (float*)d_out;

    cudaFuncSetAttribute(brits_main, cudaFuncAttributeMaxDynamicSharedMemorySize,
                         (int)sizeof(SM));

    k_denom<<<TT, 256>>>(masks);
    k_prepw<<<512, 256>>>(W_ih, W_hh, b_ih, b_hh);
    brits_main<<<NBLK, NTH, sizeof(SM)>>>(values, masks, deltas,
                                          Wdh, bdh, Wdx, bdx, Wh, bh, Wf, bf,
                                          Wc, bc, Wo, bo, out);
    k_fin<<<1, 32>>>(out);
}

// round 5
// speedup vs baseline: 2.2281x; 1.6445x over previous
#include <cuda_runtime.h>

typedef unsigned long long u64;
typedef unsigned int u32;

#define BATCH 4096
#define TT 48
#define FF 64
#define HH 128
#define NTH 256
#define RPB 32
#define NBLK (BATCH / RPB)   // 128
#define RS (TT * FF)         // 3072
#define IMP_N (BATCH * RS)   // 12582912

// ---------------- device scratch (no allocations allowed) ----------------
// gates weights permuted for mma fragments: [kt(32)][warp(8)][nt(8)][lane(32)][2]
__device__ float g_Wp[32 * 8 * 8 * 32 * 2];   // 512 KB, tf32-rounded
__device__ float g_bg[512];                    // b_ih + b_hh, col = 4*hu + gate
__device__ float g_invden[TT];
__device__ float g_losspart[NBLK];

// ---------------- f32x2 helpers ----------------
__device__ __forceinline__ u64 f2pack(float a, float b) {
    u64 r; asm("mov.b64 %0,{%1,%2};" : "=l"(r) : "f"(a), "f"(b)); return r;
}
__device__ __forceinline__ u64 f2dup(float a) {
    u64 r; asm("mov.b64 %0,{%1,%1};" : "=l"(r) : "f"(a)); return r;
}
__device__ __forceinline__ void f2unpack(u64 v, float& a, float& b) {
    asm("mov.b64 {%0,%1},%2;" : "=f"(a), "=f"(b) : "l"(v));
}
__device__ __forceinline__ void f2fma(u64& d, u64 a, u64 b) {
    asm("fma.rn.f32x2 %0,%1,%2,%0;" : "+l"(d) : "l"(a), "l"(b));
}
__device__ __forceinline__ float sigf(float x) {
    return __fdividef(1.f, 1.f + __expf(-x));
}
__device__ __forceinline__ float tanhf_(float x) {
    float e = __expf(2.f * x);
    return 1.f - __fdividef(2.f, e + 1.f);
}
__device__ __forceinline__ u32 tf32cvt(float x) {
    u32 r; asm("cvt.rna.tf32.f32 %0,%1;" : "=r"(r) : "f"(x)); return r;
}
__device__ __forceinline__ void mma_tf32(float* c, u32 a0, u32 a1, u32 a2, u32 a3,
                                         u32 b0, u32 b1) {
    asm("mma.sync.aligned.m16n8k8.row.col.f32.tf32.tf32.f32 "
        "{%0,%1,%2,%3},{%4,%5,%6,%7},{%8,%9},{%0,%1,%2,%3};"
        : "+f"(c[0]), "+f"(c[1]), "+f"(c[2]), "+f"(c[3])
        : "r"(a0), "r"(a1), "r"(a2), "r"(a3), "r"(b0), "r"(b1));
}

// ---------------- shared memory layout (~197 KB) ----------------
struct SM {
    u64 wdh2[64][64];    // gamma_h W: [k][ju] = (Wdh[2ju][k], Wdh[2ju+1][k])
    u64 wh2[128][32];    // x_h W
    u64 wf2[64][32];     // z_h W (diag zeroed)
    u64 wc2[128][32];    // alpha W
    float XI[256][34];   // k: 0..63 c_c | 64..127 m | 128..255 h
    float Cst[128][34];  // LSTM cell state
    float Xv[64][34];    // x values
    float Dl[64][34];    // deltas, then reused as x_c
    float GX[64][34];    // gamma_x
    float bg[512];       // gate biases, interleaved col order
    float bdh[128];
    float bh[64]; float bf[64]; float bc[64]; float wdx[64]; float bdx[64];
    float wos[128];
    float red[8];
    float bo0;
};

// ---------------- prep 1: 1/denom per t ----------------
__global__ void k_denom(const float* __restrict__ masks) {
    __shared__ float buf[256];
    int t = blockIdx.x;
    float s = 0.f;
    for (int i = threadIdx.x; i < BATCH * FF; i += 256) {
        int b = i >> 6, f = i & 63;
        s += masks[b * RS + t * FF + f];
    }
    buf[threadIdx.x] = s;
    __syncthreads();
    for (int st = 128; st; st >>= 1) {
        if (threadIdx.x < st) buf[threadIdx.x] += buf[threadIdx.x + st];
        __syncthreads();
    }
    if (threadIdx.x == 0) g_invden[t] = 1.f / (buf[0] + 1e-5f);
}

// ---------------- prep 2: mma-fragment-permuted gate weights ----------------
__global__ void k_prepw(const float* __restrict__ W_ih, const float* __restrict__ W_hh,
                        const float* __restrict__ b_ih, const float* __restrict__ b_hh) {
    int idx = blockIdx.x * 256 + threadIdx.x;     // 131072 total
    int j    = idx & 1;
    int lane = (idx >> 1) & 31;
    int nt   = (idx >> 6) & 7;
    int w    = (idx >> 9) & 7;
    int kt   = idx >> 12;                         // 0..31
    int col  = 64 * w + 8 * nt + (lane >> 2);     // interleaved: col = 4*hu + gate
    int gate = col & 3, hu = col >> 2;
    int jr = gate * 128 + hu;                     // PyTorch gate-major row
    int k = 8 * kt + (lane & 3) + 4 * j;
    float v = (k < 128) ? W_ih[jr * 128 + k] : W_hh[jr * 128 + (k - 128)];
    u32 tv = tf32cvt(v);
    g_Wp[idx] = __uint_as_float(tv);
    if (idx < 512) {
        int g2 = idx & 3, h2 = idx >> 2;
        int jr2 = g2 * 128 + h2;
        g_bg[idx] = b_ih[jr2] + b_hh[jr2];
    }
}

// ---------------- finalize: deterministic loss sum ----------------
__global__ void k_fin(float* __restrict__ out) {
    if (threadIdx.x == 0) {
        float s = 0.f;
        for (int i = 0; i < NBLK; i++) s += g_losspart[i];
        out[0] = s;
    }
}

// ---------------- main persistent recurrent kernel ----------------
__global__ void __launch_bounds__(NTH, 1) brits_main(
    const float* __restrict__ values, const float* __restrict__ masks,
    const float* __restrict__ deltas,
    const float* __restrict__ Wdh, const float* __restrict__ bdh,
    const float* __restrict__ Wdx, const float* __restrict__ bdx,
    const float* __restrict__ Wh,  const float* __restrict__ bh,
    const float* __restrict__ Wf,  const float* __restrict__ bf,
    const float* __restrict__ Wc,  const float* __restrict__ bc,
    const float* __restrict__ Wo,  const float* __restrict__ bo,
    float* __restrict__ out)
{
    extern __shared__ char smraw[];
    SM& S = *reinterpret_cast<SM*>(smraw);
    const int tid = threadIdx.x;
    const int row0 = blockIdx.x * RPB;

    // ---- stage small weights (unit-pair packed, transposed) ----
    for (int i = tid; i < 64 * 64; i += NTH) {
        int k = i & 63, ju = i >> 6;
        S.wdh2[k][ju] = f2pack(Wdh[(2 * ju) * 64 + k], Wdh[(2 * ju + 1) * 64 + k]);
    }
    for (int i = tid; i < 128 * 32; i += NTH) {
        int ju = i & 31, k = i >> 5;
        S.wh2[k][ju] = f2pack(Wh[(2 * ju) * 128 + k], Wh[(2 * ju + 1) * 128 + k]);
    }
    for (int i = tid; i < 64 * 32; i += NTH) {
        int ju = i & 31, k = i >> 5;
        float a = (2 * ju == k) ? 0.f : Wf[(2 * ju) * 64 + k];
        float b = (2 * ju + 1 == k) ? 0.f : Wf[(2 * ju + 1) * 64 + k];
        S.wf2[k][ju] = f2pack(a, b);
    }
    for (int i = tid; i < 128 * 32; i += NTH) {
        int ju = i & 31, k = i >> 5;
        S.wc2[k][ju] = f2pack(Wc[(2 * ju) * 128 + k], Wc[(2 * ju + 1) * 128 + k]);
    }
    for (int i = tid; i < 512; i += NTH) S.bg[i] = g_bg[i];
    if (tid < 128) { S.bdh[tid] = bdh[tid]; S.wos[tid] = Wo[tid]; }
    if (tid < 64) {
        S.bh[tid] = bh[tid]; S.bf[tid] = bf[tid]; S.bc[tid] = bc[tid];
        S.wdx[tid] = Wdx[tid * 64 + tid]; S.bdx[tid] = bdx[tid];
    }
    if (tid == 0) S.bo0 = bo[0];
    // zero h and c
    for (int i = tid; i < 128 * 34; i += NTH) {
        S.Cst[i / 34][i % 34] = 0.f;
        S.XI[128 + i / 34][i % 34] = 0.f;
    }
    __syncthreads();

    // ---- prologue: load t=0 inputs + gamma_x ----
    #pragma unroll
    for (int j = 0; j < 8; j++) {
        int i = tid + j * NTH;
        int r = i >> 6, f = i & 63;
        int g = (row0 + r) * RS + 0 * FF + f;
        float x = values[g], m = masks[g], d = deltas[g];
        S.Xv[f][r] = x;
        S.XI[64 + f][r] = m;
        S.Dl[f][r] = d;
        S.GX[f][r] = __expf(-fmaxf(d * S.wdx[f] + S.bdx[f], 0.f));
    }
    __syncthreads();

    const int rg1 = tid & 7, ug1 = tid >> 3;   // p1
    const int rg2 = tid & 7, fg2 = tid >> 3;   // p2/p3
    const int warp = tid >> 5, lane = tid & 31;
    const int q = lane & 3, gr = lane >> 2;    // mma fragment coords
    float loss_acc = 0.f;
    float* outImp = out + 1;

    for (int t = 0; t < TT; ++t) {
        // ---- p1: gamma_h GEMM (k=64) -> h *= gh ----
        {
            u64 acc[4][2];
            u64 b0 = f2pack(S.bdh[4 * ug1],     S.bdh[4 * ug1 + 1]);
            u64 b1 = f2pack(S.bdh[4 * ug1 + 2], S.bdh[4 * ug1 + 3]);
            #pragma unroll
            for (int rr = 0; rr < 4; rr++) { acc[rr][0] = b0; acc[rr][1] = b1; }
            #pragma unroll 4
            for (int k = 0; k < 64; k++) {
                u64 w0 = S.wdh2[k][2 * ug1], w1 = S.wdh2[k][2 * ug1 + 1];
                #pragma unroll
                for (int h = 0; h < 2; h++) {
                    float2 ap = *(const float2*)&S.Dl[k][4 * rg1 + 2 * h];
                    u64 a0 = f2dup(ap.x), a1 = f2dup(ap.y);
                    f2fma(acc[2 * h][0], a0, w0);
                    f2fma(acc[2 * h][1], a0, w1);
                    f2fma(acc[2 * h + 1][0], a1, w0);
                    f2fma(acc[2 * h + 1][1], a1, w1);
                }
            }
            #pragma unroll
            for (int rr = 0; rr < 4; rr++) {
                int row = 4 * rg1 + rr;
                #pragma unroll
                for (int j = 0; j < 2; j++) {
                    float z0, z1; f2unpack(acc[rr][j], z0, z1);
                    int u = 4 * ug1 + 2 * j;
                    S.XI[128 + u][row]     *= __expf(-fmaxf(z0, 0.f));
                    S.XI[128 + u + 1][row] *= __expf(-fmaxf(z1, 0.f));
                }
            }
        }
        __syncthreads();

        // ---- p2: x_h GEMM (k=128) + loss1 + x_c -> Dl ----
        float xh_r[4][2];
        float s_loss = 0.f;
        {
            u64 acc[4];
            u64 binit = f2pack(S.bh[2 * fg2], S.bh[2 * fg2 + 1]);
            #pragma unroll
            for (int rr = 0; rr < 4; rr++) acc[rr] = binit;
            #pragma unroll 4
            for (int k = 0; k < 128; k++) {
                u64 w = S.wh2[k][fg2];
                #pragma unroll
                for (int h = 0; h < 2; h++) {
                    float2 ap = *(const float2*)&S.XI[128 + k][4 * rg2 + 2 * h];
                    f2fma(acc[2 * h],     f2dup(ap.x), w);
                    f2fma(acc[2 * h + 1], f2dup(ap.y), w);
                }
            }
            #pragma unroll
            for (int rr = 0; rr < 4; rr++) {
                int row = 4 * rg2 + rr;
                f2unpack(acc[rr], xh_r[rr][0], xh_r[rr][1]);
                #pragma unroll
                for (int s = 0; s < 2; s++) {
                    int f = 2 * fg2 + s;
                    float x = S.Xv[f][row], m = S.XI[64 + f][row];
                    float xh = xh_r[rr][s];
                    s_loss += fabsf(x - xh) * m;
                    S.Dl[f][row] = m * x + (1.f - m) * xh;
                }
            }
        }
        __syncthreads();

        // ---- p3: z_h GEMM (k=64) + alpha GEMM (k=128) + c_h/c_c + losses ----
        {
            u64 az[4], aa[4];
            u64 bz = f2pack(S.bf[2 * fg2], S.bf[2 * fg2 + 1]);
            u64 ba = f2pack(S.bc[2 * fg2], S.bc[2 * fg2 + 1]);
            #pragma unroll
            for (int rr = 0; rr < 4; rr++) { az[rr] = bz; aa[rr] = ba; }
            #pragma unroll 2
            for (int k = 0; k < 64; k++) {
                u64 wz = S.wf2[k][fg2], wa = S.wc2[k][fg2];
                #pragma unroll
                for (int rr = 0; rr < 4; rr++) {
                    int row = 4 * rg2 + rr;
                    u64 axc = f2dup(S.Dl[k][row]); f2fma(az[rr], axc, wz);
                    u64 agx = f2dup(S.GX[k][row]); f2fma(aa[rr], agx, wa);
                }
            }
            #pragma unroll 2
            for (int k = 64; k < 128; k++) {
                u64 wa = S.wc2[k][fg2];
                #pragma unroll
                for (int rr = 0; rr < 4; rr++) {
                    u64 am = f2dup(S.XI[k][4 * rg2 + rr]);   // m region
                    f2fma(aa[rr], am, wa);
                }
            }
            #pragma unroll
            for (int rr = 0; rr < 4; rr++) {
                int row = 4 * rg2 + rr;
                float zh0, zh1, al0, al1;
                f2unpack(az[rr], zh0, zh1);
                f2unpack(aa[rr], al0, al1);
                #pragma unroll
                for (int s = 0; s < 2; s++) {
                    int f = 2 * fg2 + s;
                    float zh = s ? zh1 : zh0, al = s ? al1 : al0;
                    float x = S.Xv[f][row], m = S.XI[64 + f][row];
                    float xh = xh_r[rr][s];
                    float ch = al * zh + (1.f - al) * xh;
                    s_loss += (fabsf(x - zh) + fabsf(x - ch)) * m;
                    S.XI[f][row] = m * x + (1.f - m) * ch;   // c_c
                }
            }
            loss_acc += s_loss * g_invden[t];
        }
        __syncthreads();

        // ---- p4: gates GEMM via mma.sync tf32 (M32 N512 K256) + LSTM ----
        {
            // prefetch next step's inputs during the GEMM
            float px[8], pm[8], pd[8];
            const bool havenext = (t + 1 < TT);
            if (havenext) {
                #pragma unroll
                for (int j = 0; j < 8; j++) {
                    int i = tid + j * NTH;
                    int g = (row0 + (i >> 6)) * RS + (t + 1) * FF + (i & 63);
                    px[j] = values[g]; pm[j] = masks[g]; pd[j] = deltas[g];
                }
            }

            // accumulators init from bias (c0/c2 col 2q, c1/c3 col 2q+1)
            float c[2][8][4];
            #pragma unroll
            for (int nt = 0; nt < 8; nt++) {
                float b0v = S.bg[64 * warp + 8 * nt + 2 * q];
                float b1v = S.bg[64 * warp + 8 * nt + 2 * q + 1];
                #pragma unroll
                for (int mt = 0; mt < 2; mt++) {
                    c[mt][nt][0] = b0v; c[mt][nt][1] = b1v;
                    c[mt][nt][2] = b0v; c[mt][nt][3] = b1v;
                }
            }

            const uint2* wp = reinterpret_cast<const uint2*>(g_Wp);
            u32 bb[2][8][2];
            #pragma unroll
            for (int nt = 0; nt < 8; nt++) {
                uint2 v = __ldg(wp + (size_t)(((0 * 8 + warp) * 8 + nt) * 32 + lane));
                bb[0][nt][0] = v.x; bb[0][nt][1] = v.y;
            }
            #pragma unroll 2
            for (int kt = 0; kt < 32; kt++) {
                const int cur = kt & 1;
                if (kt < 31) {
                    #pragma unroll
                    for (int nt = 0; nt < 8; nt++) {
                        uint2 v = __ldg(wp + (size_t)((((kt + 1) * 8 + warp) * 8 + nt) * 32 + lane));
                        bb[cur ^ 1][nt][0] = v.x; bb[cur ^ 1][nt][1] = v.y;
                    }
                }
                const int kb = 8 * kt;
                #pragma unroll
                for (int mt = 0; mt < 2; mt++) {
                    const int r0 = 16 * mt + gr;
                    u32 a0 = tf32cvt(S.XI[kb + q][r0]);
                    u32 a1 = tf32cvt(S.XI[kb + q][r0 + 8]);
                    u32 a2 = tf32cvt(S.XI[kb + q + 4][r0]);
                    u32 a3 = tf32cvt(S.XI[kb + q + 4][r0 + 8]);
                    #pragma unroll
                    for (int nt = 0; nt < 8; nt++)
                        mma_tf32(c[mt][nt], a0, a1, a2, a3,
                                 bb[cur][nt][0], bb[cur][nt][1]);
                }
            }
            __syncthreads();   // all XI reads done before writebacks

            // LSTM epilogue: lane-pair exchange -> full i,f,g,o per lane
            const bool odd = (q & 1);
            #pragma unroll
            for (int mt = 0; mt < 2; mt++) {
                #pragma unroll
                for (int nt = 0; nt < 8; nt++) {
                    float e0 = __shfl_xor_sync(0xffffffffu, c[mt][nt][0], 1);
                    float e1 = __shfl_xor_sync(0xffffffffu, c[mt][nt][1], 1);
                    float e2 = __shfl_xor_sync(0xffffffffu, c[mt][nt][2], 1);
                    float e3 = __shfl_xor_sync(0xffffffffu, c[mt][nt][3], 1);
                    float iv, fv, gv, ov;
                    int row = 16 * mt + gr + (odd ? 8 : 0);
                    if (!odd) { iv = c[mt][nt][0]; fv = c[mt][nt][1]; gv = e0; ov = e1; }
                    else      { iv = e2; fv = e3; gv = c[mt][nt][2]; ov = c[mt][nt][3]; }
                    int hu = 16 * warp + 2 * nt + (q >> 1);
                    float co = S.Cst[hu][row];
                    float cn = sigf(fv) * co + sigf(iv) * tanhf_(gv);
                    float hn = sigf(ov) * tanhf_(cn);
                    S.Cst[hu][row] = cn;
                    S.XI[128 + hu][row] = hn;
                }
            }

            // coalesced imputation write (c_c from SMEM)
            #pragma unroll
            for (int j = 0; j < 8; j++) {
                int i = tid + j * NTH;
                int r = i >> 6, f = i & 63;
                outImp[(row0 + r) * RS + t * FF + f] = S.XI[f][r];
            }

            // store prefetched next-step inputs + gamma_x
            if (havenext) {
                #pragma unroll
                for (int j = 0; j < 8; j++) {
                    int i = tid + j * NTH;
                    int r = i >> 6, f = i & 63;
                    S.Xv[f][r] = px[j];
                    S.XI[64 + f][r] = pm[j];
                    S.Dl[f][r] = pd[j];
                    S.GX[f][r] = __expf(-fmaxf(pd[j] * S.wdx[f] + S.bdx[f], 0.f));
                }
            }
        }
        __syncthreads();
    }

    // ---- loss block-reduce (deterministic per block) ----
    float v = loss_acc;
    #pragma unroll
    for (int o = 16; o; o >>= 1) v += __shfl_down_sync(0xffffffffu, v, o);
    if ((tid & 31) == 0) S.red[tid >> 5] = v;
    __syncthreads();
    if (tid == 0) {
        float s = 0.f;
        for (int w = 0; w < 8; w++) s += S.red[w];
        g_losspart[blockIdx.x] = s;
    }

    // ---- predictions ----
    if (tid < RPB) {
        float p = S.bo0;
        #pragma unroll 4
        for (int u = 0; u < 128; u++) p += S.XI[128 + u][tid] * S.wos[u];
        out[1 + IMP_N + row0 + tid] = p;
    }
}

extern "C" void kernel_launch(void* const* d_in, const int* in_sizes, int n_in,
                              void* d_out, int out_size) {
    const float* values = (const float*)d_in[0];
    const float* masks  = (const float*)d_in[1];
    const float* deltas = (const float*)d_in[2];
    const float* Wdh = (const float*)d_in[3];
    const float* bdh = (const float*)d_in[4];
    const float* Wdx = (const float*)d_in[5];
    const float* bdx = (const float*)d_in[6];
    const float* Wh  = (const float*)d_in[7];
    const float* bh  = (const float*)d_in[8];
    const float* Wf  = (const float*)d_in[9];
    const float* bf  = (const float*)d_in[10];
    const float* Wc  = (const float*)d_in[11];
    const float* bc  = (const float*)d_in[12];
    const float* W_ih = (const float*)d_in[13];
    const float* W_hh = (const float*)d_in[14];
    const float* b_ih = (const float*)d_in[15];
    const float* b_hh = (const float*)d_in[16];
    const float* Wo  = (const float*)d_in[17];
    const float* bo  = (const float*)d_in[18];
    float* out = (float*)d_out;

    cudaFuncSetAttribute(brits_main, cudaFuncAttributeMaxDynamicSharedMemorySize,
                         (int)sizeof(SM));

    k_denom<<<TT, 256>>>(masks);
    k_prepw<<<512, 256>>>(W_ih, W_hh, b_ih, b_hh);
    brits_main<<<NBLK, NTH, sizeof(SM)>>>(values, masks, deltas,
                                          Wdh, bdh, Wdx, bdx, Wh, bh, Wf, bf,
                                          Wc, bc, Wo, bo, out);
    k_fin<<<1, 32>>>(out);
}

// round 7
// speedup vs baseline: 3.2166x; 1.4436x over previous
#include <cuda_runtime.h>

typedef unsigned long long u64;
typedef unsigned int u32;

#define BATCH 4096
#define TT 48
#define FF 64
#define HH 128
#define NTH 256
#define RPB 32
#define NBLK (BATCH / RPB)   // 128
#define RS (TT * FF)         // 3072
#define IMP_N (BATCH * RS)   // 12582912

// AF k-tile regions (each kt = 8 k-values)
#define KT_CC 0
#define KT_M  8
#define KT_H  16
#define KT_D  32
#define KT_GX 40
#define KT_XC 48
#define KT_TOT 56

// ---------------- device scratch (no allocations allowed) ----------------
// gates weights permuted for mma fragments: [kt(32)][warp(8)][nt(8)][lane(32)][2]
__device__ float g_Wp[32 * 8 * 8 * 32 * 2];   // 512 KB, tf32-rounded
__device__ float g_bg[512];                    // b_ih + b_hh, col = 4*hu + gate
__device__ float g_invden[TT];
__device__ float g_losspart[NBLK];

// ---------------- helpers ----------------
__device__ __forceinline__ float sigf(float x) {
    return __fdividef(1.f, 1.f + __expf(-x));
}
__device__ __forceinline__ float tanhf_(float x) {
    float e = __expf(2.f * x);
    return 1.f - __fdividef(2.f, e + 1.f);
}
__device__ __forceinline__ u32 tf32cvt(float x) {
    u32 r; asm("cvt.rna.tf32.f32 %0,%1;" : "=r"(r) : "f"(x)); return r;
}
__device__ __forceinline__ void mma_tf32(float* c, u32 a0, u32 a1, u32 a2, u32 a3,
                                         u32 b0, u32 b1) {
    asm("mma.sync.aligned.m16n8k8.row.col.f32.tf32.tf32.f32 "
        "{%0,%1,%2,%3},{%4,%5,%6,%7},{%8,%9},{%0,%1,%2,%3};"
        : "+f"(c[0]), "+f"(c[1]), "+f"(c[2]), "+f"(c[3])
        : "r"(a0), "r"(a1), "r"(a2), "r"(a3), "r"(b0), "r"(b1));
}
__device__ __forceinline__ void mma4(float* c, uint4 A, uint2 B) {
    mma_tf32(c, A.x, A.y, A.z, A.w, B.x, B.y);
}

// ---------------- shared memory layout (~227 KB) ----------------
struct SM {
    u32 AF[KT_TOT * 2 * 32 * 4];   // 57,344 B activation fragments (tf32)
    uint2 WdhF[8][8][2][32];       // 32 KB gamma_h B-frags (N=128)
    uint2 WhF[16][8][32];          // 32 KB x_h B-frags (N=64)
    uint2 WfF[8][8][32];           // 16 KB z_h B-frags (diag zeroed)
    uint2 WcF[16][8][32];          // 32 KB alpha B-frags
    float Xv[64][33];              // x scalar
    float Ms[64][33];              // m scalar
    float Hs[128][33];             // h scalar (carry)
    float Cst[128][33];            // LSTM c
    float bg[512];
    float bdh[128];
    float bh[64]; float bf[64]; float bc[64]; float wdx[64]; float bdx[64];
    float wos[128];
    float invden[TT];
    float red[8];
    float bo0;
};

__device__ __forceinline__ void af_store(u32* AF, int ktbase, int k, int row, float v) {
    int kt = ktbase + (k >> 3), kq = k & 7;
    int mt = row >> 4, r = row & 15;
    int lane = 4 * (r & 7) + (kq & 3);
    int slot = ((kq >> 2) << 1) | (r >> 3);
    AF[(((kt * 2 + mt) * 32 + lane) << 2) + slot] = tf32cvt(v);
}
__device__ __forceinline__ uint4 af_ld(const u32* AF, int kt, int mt, int lane) {
    return *reinterpret_cast<const uint4*>(AF + (((kt * 2 + mt) * 32 + lane) << 2));
}

// ---------------- prep 1: 1/denom per t ----------------
__global__ void k_denom(const float* __restrict__ masks) {
    __shared__ float buf[256];
    int t = blockIdx.x;
    float s = 0.f;
    for (int i = threadIdx.x; i < BATCH * FF; i += 256) {
        int b = i >> 6, f = i & 63;
        s += masks[b * RS + t * FF + f];
    }
    buf[threadIdx.x] = s;
    __syncthreads();
    for (int st = 128; st; st >>= 1) {
        if (threadIdx.x < st) buf[threadIdx.x] += buf[threadIdx.x + st];
        __syncthreads();
    }
    if (threadIdx.x == 0) g_invden[t] = 1.f / (buf[0] + 1e-5f);
}

// ---------------- prep 2: mma-fragment-permuted gate weights ----------------
__global__ void k_prepw(const float* __restrict__ W_ih, const float* __restrict__ W_hh,
                        const float* __restrict__ b_ih, const float* __restrict__ b_hh) {
    int idx = blockIdx.x * 256 + threadIdx.x;     // 131072 total
    int j    = idx & 1;
    int lane = (idx >> 1) & 31;
    int nt   = (idx >> 6) & 7;
    int w    = (idx >> 9) & 7;
    int kt   = idx >> 12;                         // 0..31
    int col  = 64 * w + 8 * nt + (lane >> 2);     // interleaved: col = 4*hu + gate
    int gate = col & 3, hu = col >> 2;
    int jr = gate * 128 + hu;                     // PyTorch gate-major row
    int k = 8 * kt + (lane & 3) + 4 * j;
    float v = (k < 128) ? W_ih[jr * 128 + k] : W_hh[jr * 128 + (k - 128)];
    g_Wp[idx] = __uint_as_float(tf32cvt(v));
    if (idx < 512) {
        int g2 = idx & 3, h2 = idx >> 2;
        int jr2 = g2 * 128 + h2;
        g_bg[idx] = b_ih[jr2] + b_hh[jr2];
    }
}

// ---------------- finalize: deterministic loss sum ----------------
__global__ void k_fin(float* __restrict__ out) {
    if (threadIdx.x == 0) {
        float s = 0.f;
        for (int i = 0; i < NBLK; i++) s += g_losspart[i];
        out[0] = s;
    }
}

// ---------------- main persistent recurrent kernel ----------------
__global__ void __launch_bounds__(NTH, 1) brits_main(
    const float* __restrict__ values, const float* __restrict__ masks,
    const float* __restrict__ deltas,
    const float* __restrict__ Wdh, const float* __restrict__ bdh,
    const float* __restrict__ Wdx, const float* __restrict__ bdx,
    const float* __restrict__ Wh,  const float* __restrict__ bh,
    const float* __restrict__ Wf,  const float* __restrict__ bf,
    const float* __restrict__ Wc,  const float* __restrict__ bc,
    const float* __restrict__ Wo,  const float* __restrict__ bo,
    float* __restrict__ out)
{
    extern __shared__ char smraw[];
    SM& S = *reinterpret_cast<SM*>(smraw);
    const int tid = threadIdx.x;
    const int row0 = blockIdx.x * RPB;
    const int warp = tid >> 5, lane = tid & 31;
    const int q = lane & 3, gr = lane >> 2;

    // ---- stage small-GEMM weight fragments (tf32) ----
    for (int i = tid; i < 8 * 8 * 2 * 32; i += NTH) {   // WdhF: gamma_h, N=128,K=64
        int ln = i & 31, ntl = (i >> 5) & 1, w = (i >> 6) & 7, kt = i >> 9;
        int n = 16 * w + 8 * ntl + (ln >> 2);
        int k0 = 8 * kt + (ln & 3);
        S.WdhF[kt][w][ntl][ln] = make_uint2(tf32cvt(Wdh[n * 64 + k0]),
                                            tf32cvt(Wdh[n * 64 + k0 + 4]));
    }
    for (int i = tid; i < 16 * 8 * 32; i += NTH) {       // WhF: x_h, N=64,K=128
        int ln = i & 31, w = (i >> 5) & 7, kt = i >> 8;
        int n = 8 * w + (ln >> 2);
        int k0 = 8 * kt + (ln & 3);
        S.WhF[kt][w][ln] = make_uint2(tf32cvt(Wh[n * 128 + k0]),
                                      tf32cvt(Wh[n * 128 + k0 + 4]));
    }
    for (int i = tid; i < 8 * 8 * 32; i += NTH) {        // WfF: z_h, N=64,K=64, diag 0
        int ln = i & 31, w = (i >> 5) & 7, kt = i >> 8;
        int n = 8 * w + (ln >> 2);
        int k0 = 8 * kt + (ln & 3);
        float v0 = (n == k0)     ? 0.f : Wf[n * 64 + k0];
        float v1 = (n == k0 + 4) ? 0.f : Wf[n * 64 + k0 + 4];
        S.WfF[kt][w][ln] = make_uint2(tf32cvt(v0), tf32cvt(v1));
    }
    for (int i = tid; i < 16 * 8 * 32; i += NTH) {       // WcF: alpha, N=64,K=128
        int ln = i & 31, w = (i >> 5) & 7, kt = i >> 8;
        int n = 8 * w + (ln >> 2);
        int k0 = 8 * kt + (ln & 3);
        S.WcF[kt][w][ln] = make_uint2(tf32cvt(Wc[n * 128 + k0]),
                                      tf32cvt(Wc[n * 128 + k0 + 4]));
    }
    for (int i = tid; i < 512; i += NTH) S.bg[i] = g_bg[i];
    if (tid < 128) { S.bdh[tid] = bdh[tid]; S.wos[tid] = Wo[tid]; }
    if (tid < 64) {
        S.bh[tid] = bh[tid]; S.bf[tid] = bf[tid]; S.bc[tid] = bc[tid];
        S.wdx[tid] = Wdx[tid * 64 + tid]; S.bdx[tid] = bdx[tid];
    }
    if (tid < TT) S.invden[tid] = g_invden[tid];
    if (tid == 0) S.bo0 = bo[0];
    for (int i = tid; i < 128 * 33; i += NTH) {
        S.Hs[i / 33][i % 33] = 0.f;
        S.Cst[i / 33][i % 33] = 0.f;
    }
    __syncthreads();

    // ---- prologue: t=0 inputs -> scalars + AF(M,D,GX) ----
    #pragma unroll
    for (int j = 0; j < 8; j++) {
        int i = tid + j * NTH;
        int r = i >> 6, f = i & 63;
        int g = (row0 + r) * RS + f;
        float x = values[g], m = masks[g], d = deltas[g];
        S.Xv[f][r] = x;
        S.Ms[f][r] = m;
        af_store(S.AF, KT_M, f, r, m);
        af_store(S.AF, KT_D, f, r, d);
        af_store(S.AF, KT_GX, f, r, __expf(-fmaxf(d * S.wdx[f] + S.bdx[f], 0.f)));
    }
    __syncthreads();

    float loss_acc = 0.f;
    float* outImp = out + 1;

    for (int t = 0; t < TT; ++t) {
        // ================= p1: gamma_h mma (N=128, K=64) =================
        {
            float a[2][2][4];
            #pragma unroll
            for (int ntl = 0; ntl < 2; ntl++) {
                int colb = 16 * warp + 8 * ntl + 2 * q;
                float b0v = S.bdh[colb], b1v = S.bdh[colb + 1];
                #pragma unroll
                for (int mt = 0; mt < 2; mt++) {
                    a[mt][ntl][0] = b0v; a[mt][ntl][1] = b1v;
                    a[mt][ntl][2] = b0v; a[mt][ntl][3] = b1v;
                }
            }
            #pragma unroll
            for (int kt = 0; kt < 8; kt++) {
                uint4 A0 = af_ld(S.AF, KT_D + kt, 0, lane);
                uint4 A1 = af_ld(S.AF, KT_D + kt, 1, lane);
                #pragma unroll
                for (int ntl = 0; ntl < 2; ntl++) {
                    uint2 b = S.WdhF[kt][warp][ntl][lane];
                    mma4(a[0][ntl], A0, b);
                    mma4(a[1][ntl], A1, b);
                }
            }
            #pragma unroll
            for (int mt = 0; mt < 2; mt++)
                #pragma unroll
                for (int ntl = 0; ntl < 2; ntl++) {
                    int colb = 16 * warp + 8 * ntl + 2 * q;
                    #pragma unroll
                    for (int si = 0; si < 4; si++) {
                        int row = 16 * mt + gr + ((si >> 1) << 3);
                        int hu = colb + (si & 1);
                        float gh = __expf(-fmaxf(a[mt][ntl][si], 0.f));
                        float hn = S.Hs[hu][row] * gh;
                        S.Hs[hu][row] = hn;
                        af_store(S.AF, KT_H, hu, row, hn);
                    }
                }
        }
        __syncthreads();

        // ================= p2: x_h mma (N=64, K=128) + loss1 + x_c =================
        float xh_keep[2][4];
        float s_loss = 0.f;
        const int colb = 8 * warp + 2 * q;
        {
            float a[2][4];
            float b0v = S.bh[colb], b1v = S.bh[colb + 1];
            #pragma unroll
            for (int mt = 0; mt < 2; mt++) {
                a[mt][0] = b0v; a[mt][1] = b1v; a[mt][2] = b0v; a[mt][3] = b1v;
            }
            #pragma unroll
            for (int kt = 0; kt < 16; kt++) {
                uint4 A0 = af_ld(S.AF, KT_H + kt, 0, lane);
                uint4 A1 = af_ld(S.AF, KT_H + kt, 1, lane);
                uint2 b = S.WhF[kt][warp][lane];
                mma4(a[0], A0, b);
                mma4(a[1], A1, b);
            }
            #pragma unroll
            for (int mt = 0; mt < 2; mt++)
                #pragma unroll
                for (int si = 0; si < 4; si++) {
                    int row = 16 * mt + gr + ((si >> 1) << 3);
                    int f = colb + (si & 1);
                    float x = S.Xv[f][row], m = S.Ms[f][row];
                    float xh = a[mt][si];
                    s_loss += fabsf(x - xh) * m;
                    af_store(S.AF, KT_XC, f, row, m * x + (1.f - m) * xh);
                    xh_keep[mt][si] = xh;
                }
        }
        __syncthreads();

        // ========== p3: z_h mma (K=64) + alpha mma (K=128) + c_c + losses ==========
        {
            float az[2][4], aa[2][4];
            float bz0 = S.bf[colb], bz1 = S.bf[colb + 1];
            float ba0 = S.bc[colb], ba1 = S.bc[colb + 1];
            #pragma unroll
            for (int mt = 0; mt < 2; mt++) {
                az[mt][0] = bz0; az[mt][1] = bz1; az[mt][2] = bz0; az[mt][3] = bz1;
                aa[mt][0] = ba0; aa[mt][1] = ba1; aa[mt][2] = ba0; aa[mt][3] = ba1;
            }
            #pragma unroll
            for (int kt = 0; kt < 8; kt++) {
                uint4 A0 = af_ld(S.AF, KT_XC + kt, 0, lane);
                uint4 A1 = af_ld(S.AF, KT_XC + kt, 1, lane);
                uint2 b = S.WfF[kt][warp][lane];
                mma4(az[0], A0, b);
                mma4(az[1], A1, b);
            }
            #pragma unroll
            for (int kt = 0; kt < 8; kt++) {
                uint4 A0 = af_ld(S.AF, KT_GX + kt, 0, lane);
                uint4 A1 = af_ld(S.AF, KT_GX + kt, 1, lane);
                uint2 b = S.WcF[kt][warp][lane];
                mma4(aa[0], A0, b);
                mma4(aa[1], A1, b);
            }
            #pragma unroll
            for (int kt = 0; kt < 8; kt++) {
                uint4 A0 = af_ld(S.AF, KT_M + kt, 0, lane);
                uint4 A1 = af_ld(S.AF, KT_M + kt, 1, lane);
                uint2 b = S.WcF[8 + kt][warp][lane];
                mma4(aa[0], A0, b);
                mma4(aa[1], A1, b);
            }
            #pragma unroll
            for (int mt = 0; mt < 2; mt++)
                #pragma unroll
                for (int half = 0; half < 2; half++) {
                    int row = 16 * mt + gr + (half << 3);
                    float* op = &outImp[(row0 + row) * RS + t * FF + colb];
                    #pragma unroll
                    for (int s = 0; s < 2; s++) {
                        int si = 2 * half + s;
                        int f = colb + s;
                        float zh = az[mt][si], al = aa[mt][si];
                        float x = S.Xv[f][row], m = S.Ms[f][row];
                        float xh = xh_keep[mt][si];
                        float ch = al * zh + (1.f - al) * xh;
                        s_loss += (fabsf(x - zh) + fabsf(x - ch)) * m;
                        float cc = m * x + (1.f - m) * ch;
                        af_store(S.AF, KT_CC, f, row, cc);
                        op[s] = cc;   // scalar stores: out+1 base is only 4B-aligned
                    }
                }
            loss_acc += s_loss * S.invden[t];
        }
        __syncthreads();

        // ================= p4: gates mma (N=512, K=256) + LSTM =================
        {
            float px[8], pm[8], pd[8];
            const bool havenext = (t + 1 < TT);
            if (havenext) {
                #pragma unroll
                for (int j = 0; j < 8; j++) {
                    int i = tid + j * NTH;
                    int g = (row0 + (i >> 6)) * RS + (t + 1) * FF + (i & 63);
                    px[j] = values[g]; pm[j] = masks[g]; pd[j] = deltas[g];
                }
            }

            float c[2][8][4];
            #pragma unroll
            for (int nt = 0; nt < 8; nt++) {
                float b0v = S.bg[64 * warp + 8 * nt + 2 * q];
                float b1v = S.bg[64 * warp + 8 * nt + 2 * q + 1];
                #pragma unroll
                for (int mt = 0; mt < 2; mt++) {
                    c[mt][nt][0] = b0v; c[mt][nt][1] = b1v;
                    c[mt][nt][2] = b0v; c[mt][nt][3] = b1v;
                }
            }

            const uint2* wp = reinterpret_cast<const uint2*>(g_Wp);
            uint2 bb[2][8];
            #pragma unroll
            for (int nt = 0; nt < 8; nt++)
                bb[0][nt] = __ldg(wp + (size_t)(((0 * 8 + warp) * 8 + nt) * 32 + lane));
            #pragma unroll 2
            for (int kt = 0; kt < 32; kt++) {
                const int cur = kt & 1;
                if (kt < 31) {
                    #pragma unroll
                    for (int nt = 0; nt < 8; nt++)
                        bb[cur ^ 1][nt] =
                            __ldg(wp + (size_t)((((kt + 1) * 8 + warp) * 8 + nt) * 32 + lane));
                }
                uint4 A0 = af_ld(S.AF, kt, 0, lane);
                uint4 A1 = af_ld(S.AF, kt, 1, lane);
                #pragma unroll
                for (int nt = 0; nt < 8; nt++) {
                    mma4(c[0][nt], A0, bb[cur][nt]);
                    mma4(c[1][nt], A1, bb[cur][nt]);
                }
            }
            __syncthreads();   // all AF reads done before overwrites

            // LSTM epilogue: lane-pair exchange -> full i,f,g,o per lane
            const bool odd = (q & 1);
            #pragma unroll
            for (int mt = 0; mt < 2; mt++) {
                #pragma unroll
                for (int nt = 0; nt < 8; nt++) {
                    float e0 = __shfl_xor_sync(0xffffffffu, c[mt][nt][0], 1);
                    float e1 = __shfl_xor_sync(0xffffffffu, c[mt][nt][1], 1);
                    float e2 = __shfl_xor_sync(0xffffffffu, c[mt][nt][2], 1);
                    float e3 = __shfl_xor_sync(0xffffffffu, c[mt][nt][3], 1);
                    float iv, fv, gv, ov;
                    int row = 16 * mt + gr + (odd ? 8 : 0);
                    if (!odd) { iv = c[mt][nt][0]; fv = c[mt][nt][1]; gv = e0; ov = e1; }
                    else      { iv = e2; fv = e3; gv = c[mt][nt][2]; ov = c[mt][nt][3]; }
                    int hu = 16 * warp + 2 * nt + (q >> 1);
                    float co = S.Cst[hu][row];
                    float cn = sigf(fv) * co + sigf(iv) * tanhf_(gv);
                    float hn = sigf(ov) * tanhf_(cn);
                    S.Cst[hu][row] = cn;
                    S.Hs[hu][row] = hn;
                }
            }

            // next-step inputs -> scalars + AF(M,D,GX)
            if (havenext) {
                #pragma unroll
                for (int j = 0; j < 8; j++) {
                    int i = tid + j * NTH;
                    int r = i >> 6, f = i & 63;
                    S.Xv[f][r] = px[j];
                    S.Ms[f][r] = pm[j];
                    af_store(S.AF, KT_M, f, r, pm[j]);
                    af_store(S.AF, KT_D, f, r, pd[j]);
                    af_store(S.AF, KT_GX, f, r,
                             __expf(-fmaxf(pd[j] * S.wdx[f] + S.bdx[f], 0.f)));
                }
            }
        }
        __syncthreads();
    }

    // ---- loss block-reduce (deterministic per block) ----
    float v = loss_acc;
    #pragma unroll
    for (int o = 16; o; o >>= 1) v += __shfl_down_sync(0xffffffffu, v, o);
    if ((tid & 31) == 0) S.red[tid >> 5] = v;
    __syncthreads();
    if (tid == 0) {
        float s = 0.f;
        for (int w = 0; w < 8; w++) s += S.red[w];
        g_losspart[blockIdx.x] = s;
    }

    // ---- predictions ----
    if (tid < RPB) {
        float p = S.bo0;
        #pragma unroll 4
        for (int u = 0; u < 128; u++) p += S.Hs[u][tid] * S.wos[u];
        out[1 + IMP_N + row0 + tid] = p;
    }
}

extern "C" void kernel_launch(void* const* d_in, const int* in_sizes, int n_in,
                              void* d_out, int out_size) {
    const float* values = (const float*)d_in[0];
    const float* masks  = (const float*)d_in[1];
    const float* deltas = (const float*)d_in[2];
    const float* Wdh = (const float*)d_in[3];
    const float* bdh = (const float*)d_in[4];
    const float* Wdx = (const float*)d_in[5];
    const float* bdx = (const float*)d_in[6];
    const float* Wh  = (const float*)d_in[7];
    const float* bh  = (const float*)d_in[8];
    const float* Wf  = (const float*)d_in[9];
    const float* bf  = (const float*)d_in[10];
    const float* Wc  = (const float*)d_in[11];
    const float* bc  = (const float*)d_in[12];
    const float* W_ih = (const float*)d_in[13];
    const float* W_hh = (const float*)d_in[14];
    const float* b_ih = (const float*)d_in[15];
    const float* b_hh = (const float*)d_in[16];
    const float* Wo  = (const float*)d_in[17];
    const float* bo  = (const float*)d_in[18];
    float* out = (float*)d_out;

    cudaFuncSetAttribute(brits_main, cudaFuncAttributeMaxDynamicSharedMemorySize,
                         (int)sizeof(SM));

    k_denom<<<TT, 256>>>(masks);
    k_prepw<<<512, 256>>>(W_ih, W_hh, b_ih, b_hh);
    brits_main<<<NBLK, NTH, sizeof(SM)>>>(values, masks, deltas,
                                          Wdh, bdh, Wdx, bdx, Wh, bh, Wf, bf,
                                          Wc, bc, Wo, bo, out);
    k_fin<<<1, 32>>>(out);
}

// round 9
// speedup vs baseline: 4.6151x; 1.4348x over previous
#include <cuda_runtime.h>
#include <cuda_fp16.h>

typedef unsigned long long u64;
typedef unsigned int u32;

#define BATCH 4096
#define TT 48
#define FF 64
#define HH 128
#define NTH 512
#define RPB 32
#define NBLK (BATCH / RPB)   // 128
#define RS (TT * FF)         // 3072
#define IMP_N (BATCH * RS)   // 12582912

// AF k-tile regions (each kt = 16 k-values)
#define KT_CC 0
#define KT_M  4
#define KT_H  8
#define KT_D  16
#define KT_GX 20
#define KT_XC 24
#define KT_TOT 28

// ---------------- device scratch (no allocations allowed) ----------------
// gates weights (fp16) in mma B-frag layout: [kt(16)][nt(64)][lane(32)] uint2
__device__ uint2 g_Wp[16 * 64 * 32];   // 256 KB
__device__ float g_bg[512];            // b_ih + b_hh, col = 4*hu + gate
__device__ float g_invden[TT];
__device__ float g_losspart[NBLK];

// ---------------- helpers ----------------
__device__ __forceinline__ float sigf(float x) {
    return __fdividef(1.f, 1.f + __expf(-x));
}
__device__ __forceinline__ float tanhf_(float x) {
    float e = __expf(2.f * x);
    return 1.f - __fdividef(2.f, e + 1.f);
}
__device__ __forceinline__ u32 h2pack(float lo, float hi) {
    u32 r;
    asm("cvt.rn.f16x2.f32 %0, %2, %1;" : "=r"(r) : "f"(lo), "f"(hi));
    return r;
}
__device__ __forceinline__ void mma_f16(float* c, u32 a0, u32 a1, u32 a2, u32 a3,
                                        u32 b0, u32 b1) {
    asm("mma.sync.aligned.m16n8k16.row.col.f32.f16.f16.f32 "
        "{%0,%1,%2,%3},{%4,%5,%6,%7},{%8,%9},{%0,%1,%2,%3};"
        : "+f"(c[0]), "+f"(c[1]), "+f"(c[2]), "+f"(c[3])
        : "r"(a0), "r"(a1), "r"(a2), "r"(a3), "r"(b0), "r"(b1));
}
__device__ __forceinline__ void mma4(float* c, uint4 A, uint2 B) {
    mma_f16(c, A.x, A.y, A.z, A.w, B.x, B.y);
}

// ---------------- shared memory layout (~139 KB) ----------------
struct SM {
    u32 AF[KT_TOT * 2 * 32 * 4];   // 28,672 B fp16 A-fragments
    uint2 WdhF[4][16][32];         // 16 KB gamma_h B-frags (N=128)
    uint2 WhF[8][8][32];           // 16 KB x_h B-frags (N=64)
    uint2 WfF[4][8][32];           // 8 KB z_h (diag zeroed)
    uint2 WcF[8][8][32];           // 16 KB alpha
    float Xv[64][33];              // x scalar (fp32)
    float Ms[64][33];              // m scalar
    float Hs[128][33];             // h carry (fp32)
    float Cst[128][33];            // LSTM c (fp32)
    float bg[512];
    float bdh[128];
    float bh[64]; float bf[64]; float bc[64]; float wdx[64]; float bdx[64];
    float wos[128];
    float invden[TT];
    float red[16];
    float bo0;
};

// store a pair of adjacent-k values (k0 even) as one fp16x2 word
__device__ __forceinline__ void af_storep(u32* AF, int ktbase, int k0, int row,
                                          float v0, float v1) {
    int kt = ktbase + (k0 >> 4), kq = k0 & 15;
    int mt = row >> 4, r = row & 15;
    int ln = 4 * (r & 7) + ((kq & 7) >> 1);
    int slot = (r >> 3) | ((kq >> 3) << 1);
    AF[(((kt * 2 + mt) * 32 + ln) << 2) + slot] = h2pack(v0, v1);
}
__device__ __forceinline__ uint4 af_ld(const u32* AF, int kt, int mt, int lane) {
    return *reinterpret_cast<const uint4*>(AF + (((kt * 2 + mt) * 32 + lane) << 2));
}

// ---------------- prep 1: 1/denom per t ----------------
__global__ void k_denom(const float* __restrict__ masks) {
    __shared__ float buf[256];
    int t = blockIdx.x;
    float s = 0.f;
    for (int i = threadIdx.x; i < BATCH * FF; i += 256) {
        int b = i >> 6, f = i & 63;
        s += masks[b * RS + t * FF + f];
    }
    buf[threadIdx.x] = s;
    __syncthreads();
    for (int st = 128; st; st >>= 1) {
        if (threadIdx.x < st) buf[threadIdx.x] += buf[threadIdx.x + st];
        __syncthreads();
    }
    if (threadIdx.x == 0) g_invden[t] = 1.f / (buf[0] + 1e-5f);
}

// ---------------- prep 2: fp16 B-frag gate weights ----------------
__global__ void k_prepw(const float* __restrict__ W_ih, const float* __restrict__ W_hh,
                        const float* __restrict__ b_ih, const float* __restrict__ b_hh) {
    int idx = blockIdx.x * 256 + threadIdx.x;     // 32768 total
    int lane = idx & 31;
    int nt   = (idx >> 5) & 63;
    int kt   = idx >> 11;                         // 0..15
    int col  = 8 * nt + (lane >> 2);              // interleaved: col = 4*hu + gate
    int gate = col & 3, hu = col >> 2;
    int jr = gate * 128 + hu;                     // PyTorch gate-major row
    int k0 = 16 * kt + 2 * (lane & 3);
    #define WGET(k) ((k) < 128 ? W_ih[jr * 128 + (k)] : W_hh[jr * 128 + (k) - 128])
    g_Wp[idx] = make_uint2(h2pack(WGET(k0), WGET(k0 + 1)),
                           h2pack(WGET(k0 + 8), WGET(k0 + 9)));
    #undef WGET
    if (idx < 512) {
        int g2 = idx & 3, h2 = idx >> 2;
        int jr2 = g2 * 128 + h2;
        g_bg[idx] = b_ih[jr2] + b_hh[jr2];
    }
}

// ---------------- finalize: deterministic loss sum ----------------
__global__ void k_fin(float* __restrict__ out) {
    if (threadIdx.x == 0) {
        float s = 0.f;
        for (int i = 0; i < NBLK; i++) s += g_losspart[i];
        out[0] = s;
    }
}

// ---------------- main persistent recurrent kernel ----------------
__global__ void __launch_bounds__(NTH, 1) brits_main(
    const float* __restrict__ values, const float* __restrict__ masks,
    const float* __restrict__ deltas,
    const float* __restrict__ Wdh, const float* __restrict__ bdh,
    const float* __restrict__ Wdx, const float* __restrict__ bdx,
    const float* __restrict__ Wh,  const float* __restrict__ bh,
    const float* __restrict__ Wf,  const float* __restrict__ bf,
    const float* __restrict__ Wc,  const float* __restrict__ bc,
    const float* __restrict__ Wo,  const float* __restrict__ bo,
    float* __restrict__ out)
{
    extern __shared__ char smraw[];
    SM& S = *reinterpret_cast<SM*>(smraw);
    const int tid = threadIdx.x;
    const int row0 = blockIdx.x * RPB;
    const int warp = tid >> 5, lane = tid & 31;
    const int q = lane & 3, gr = lane >> 2;

    // ---- stage small-GEMM B-fragments (fp16) ----
    for (int i = tid; i < 4 * 16 * 32; i += NTH) {        // WdhF: gamma_h N=128 K=64
        int ln = i & 31, w = (i >> 5) & 15, kt = i >> 9;
        int n = 8 * w + (ln >> 2);
        int kk = 16 * kt + 2 * (ln & 3);
        S.WdhF[kt][w][ln] = make_uint2(
            h2pack(Wdh[n * 64 + kk],     Wdh[n * 64 + kk + 1]),
            h2pack(Wdh[n * 64 + kk + 8], Wdh[n * 64 + kk + 9]));
    }
    for (int i = tid; i < 8 * 8 * 32; i += NTH) {         // WhF: x_h N=64 K=128
        int ln = i & 31, nt = (i >> 5) & 7, kt = i >> 8;
        int n = 8 * nt + (ln >> 2);
        int kk = 16 * kt + 2 * (ln & 3);
        S.WhF[kt][nt][ln] = make_uint2(
            h2pack(Wh[n * 128 + kk],     Wh[n * 128 + kk + 1]),
            h2pack(Wh[n * 128 + kk + 8], Wh[n * 128 + kk + 9]));
    }
    for (int i = tid; i < 4 * 8 * 32; i += NTH) {         // WfF: z_h N=64 K=64 diag 0
        int ln = i & 31, nt = (i >> 5) & 7, kt = i >> 8;
        int n = 8 * nt + (ln >> 2);
        int kk = 16 * kt + 2 * (ln & 3);
        #define WFGET(k) ((n == (k)) ? 0.f : Wf[n * 64 + (k)])
        S.WfF[kt][nt][ln] = make_uint2(
            h2pack(WFGET(kk), WFGET(kk + 1)),
            h2pack(WFGET(kk + 8), WFGET(kk + 9)));
        #undef WFGET
    }
    for (int i = tid; i < 8 * 8 * 32; i += NTH) {         // WcF: alpha N=64 K=128
        int ln = i & 31, nt = (i >> 5) & 7, kt = i >> 8;
        int n = 8 * nt + (ln >> 2);
        int kk = 16 * kt + 2 * (ln & 3);
        S.WcF[kt][nt][ln] = make_uint2(
            h2pack(Wc[n * 128 + kk],     Wc[n * 128 + kk + 1]),
            h2pack(Wc[n * 128 + kk + 8], Wc[n * 128 + kk + 9]));
    }
    for (int i = tid; i < 512; i += NTH) S.bg[i] = g_bg[i];
    if (tid < 128) { S.bdh[tid] = bdh[tid]; S.wos[tid] = Wo[tid]; }
    if (tid < 64) {
        S.bh[tid] = bh[tid]; S.bf[tid] = bf[tid]; S.bc[tid] = bc[tid];
        S.wdx[tid] = Wdx[tid * 64 + tid]; S.bdx[tid] = bdx[tid];
    }
    if (tid < TT) S.invden[tid] = g_invden[tid];
    if (tid == 0) S.bo0 = bo[0];
    for (int i = tid; i < 128 * 33; i += NTH) {
        S.Hs[i / 33][i % 33] = 0.f;
        S.Cst[i / 33][i % 33] = 0.f;
    }
    __syncthreads();

    // ---- prologue: t=0 inputs (float2 coalesced) -> scalars + AF(M,D,GX) ----
    #pragma unroll
    for (int j = 0; j < 2; j++) {
        int row = warp + 16 * j;                 // r in [0,32)
        int f0 = 2 * lane;
        int g = (row0 + row) * RS + f0;
        float2 xv = *reinterpret_cast<const float2*>(values + g);
        float2 mv = *reinterpret_cast<const float2*>(masks + g);
        float2 dv = *reinterpret_cast<const float2*>(deltas + g);
        S.Xv[f0][row] = xv.x;  S.Xv[f0 + 1][row] = xv.y;
        S.Ms[f0][row] = mv.x;  S.Ms[f0 + 1][row] = mv.y;
        af_storep(S.AF, KT_M, f0, row, mv.x, mv.y);
        af_storep(S.AF, KT_D, f0, row, dv.x, dv.y);
        float g0 = __expf(-fmaxf(dv.x * S.wdx[f0]     + S.bdx[f0],     0.f));
        float g1 = __expf(-fmaxf(dv.y * S.wdx[f0 + 1] + S.bdx[f0 + 1], 0.f));
        af_storep(S.AF, KT_GX, f0, row, g0, g1);
    }
    __syncthreads();

    float loss_acc = 0.f;
    float* outImp = out + 1;
    const int wmt = warp >> 3;      // mt for p2/p3
    const int wnt = warp & 7;       // ntile for p2/p3
    const int colb = 8 * wnt + 2 * q;

    for (int t = 0; t < TT; ++t) {
        // ===== p1: gamma_h mma (N=128, K=64). warp w -> cols 8w..8w+7, both mt =====
        {
            float a[2][4];
            int cb1 = 8 * warp + 2 * q;
            float b0v = S.bdh[cb1], b1v = S.bdh[cb1 + 1];
            #pragma unroll
            for (int mt = 0; mt < 2; mt++) {
                a[mt][0] = b0v; a[mt][1] = b1v; a[mt][2] = b0v; a[mt][3] = b1v;
            }
            #pragma unroll
            for (int kt = 0; kt < 4; kt++) {
                uint4 A0 = af_ld(S.AF, KT_D + kt, 0, lane);
                uint4 A1 = af_ld(S.AF, KT_D + kt, 1, lane);
                uint2 b = S.WdhF[kt][warp][lane];
                mma4(a[0], A0, b);
                mma4(a[1], A1, b);
            }
            #pragma unroll
            for (int mt = 0; mt < 2; mt++)
                #pragma unroll
                for (int half = 0; half < 2; half++) {
                    int row = 16 * mt + gr + 8 * half;
                    float g0 = __expf(-fmaxf(a[mt][2 * half],     0.f));
                    float g1 = __expf(-fmaxf(a[mt][2 * half + 1], 0.f));
                    float h0 = S.Hs[cb1][row] * g0;
                    float h1 = S.Hs[cb1 + 1][row] * g1;
                    S.Hs[cb1][row] = h0;
                    S.Hs[cb1 + 1][row] = h1;
                    af_storep(S.AF, KT_H, cb1, row, h0, h1);
                }
        }
        __syncthreads();

        // ===== p2: x_h mma (N=64, K=128). warp -> mt=wmt, cols 8*wnt.. =====
        float xh_keep[4];
        float s_loss = 0.f;
        {
            float a[4];
            a[0] = S.bh[colb]; a[1] = S.bh[colb + 1]; a[2] = a[0]; a[3] = a[1];
            #pragma unroll
            for (int kt = 0; kt < 8; kt++) {
                uint4 A = af_ld(S.AF, KT_H + kt, wmt, lane);
                mma4(a, A, S.WhF[kt][wnt][lane]);
            }
            #pragma unroll
            for (int half = 0; half < 2; half++) {
                int row = 16 * wmt + gr + 8 * half;
                float xc2[2];
                #pragma unroll
                for (int s = 0; s < 2; s++) {
                    int f = colb + s;
                    float x = S.Xv[f][row], m = S.Ms[f][row];
                    float xh = a[2 * half + s];
                    s_loss += fabsf(x - xh) * m;
                    xc2[s] = m * x + (1.f - m) * xh;
                    xh_keep[2 * half + s] = xh;
                }
                af_storep(S.AF, KT_XC, colb, row, xc2[0], xc2[1]);
            }
        }
        __syncthreads();

        // ===== p3: z_h (K=64) + alpha (K=128) + c_c + losses =====
        {
            float az[4], aa[4];
            az[0] = S.bf[colb]; az[1] = S.bf[colb + 1]; az[2] = az[0]; az[3] = az[1];
            aa[0] = S.bc[colb]; aa[1] = S.bc[colb + 1]; aa[2] = aa[0]; aa[3] = aa[1];
            #pragma unroll
            for (int kt = 0; kt < 4; kt++) {
                uint4 Axc = af_ld(S.AF, KT_XC + kt, wmt, lane);
                mma4(az, Axc, S.WfF[kt][wnt][lane]);
                uint4 Agx = af_ld(S.AF, KT_GX + kt, wmt, lane);
                mma4(aa, Agx, S.WcF[kt][wnt][lane]);
                uint4 Am = af_ld(S.AF, KT_M + kt, wmt, lane);
                mma4(aa, Am, S.WcF[4 + kt][wnt][lane]);
            }
            #pragma unroll
            for (int half = 0; half < 2; half++) {
                int row = 16 * wmt + gr + 8 * half;
                float* op = &outImp[(row0 + row) * RS + t * FF + colb];
                float cc2[2];
                #pragma unroll
                for (int s = 0; s < 2; s++) {
                    int si = 2 * half + s;
                    int f = colb + s;
                    float zh = az[si], al = aa[si];
                    float x = S.Xv[f][row], m = S.Ms[f][row];
                    float xh = xh_keep[si];
                    float ch = al * zh + (1.f - al) * xh;
                    s_loss += (fabsf(x - zh) + fabsf(x - ch)) * m;
                    float cc = m * x + (1.f - m) * ch;
                    cc2[s] = cc;
                    op[s] = cc;   // scalar: out+1 base only 4B-aligned
                }
                af_storep(S.AF, KT_CC, colb, row, cc2[0], cc2[1]);
            }
            loss_acc += s_loss * S.invden[t];
        }
        __syncthreads();

        // ===== p4: gates mma (N=512, K=256). warp -> cols 32w..32w+31 =====
        {
            // prefetch next-step inputs early (overlaps the GEMM)
            float2 nx[2], nm[2], nd[2];
            const bool havenext = (t + 1 < TT);
            if (havenext) {
                #pragma unroll
                for (int j = 0; j < 2; j++) {
                    int row = warp + 16 * j;
                    int g = (row0 + row) * RS + (t + 1) * FF + 2 * lane;
                    nx[j] = *reinterpret_cast<const float2*>(values + g);
                    nm[j] = *reinterpret_cast<const float2*>(masks + g);
                    nd[j] = *reinterpret_cast<const float2*>(deltas + g);
                }
            }

            float c[2][4][4];
            #pragma unroll
            for (int ntl = 0; ntl < 4; ntl++) {
                int cb = 32 * warp + 8 * ntl + 2 * q;
                float b0v = S.bg[cb], b1v = S.bg[cb + 1];
                #pragma unroll
                for (int mt = 0; mt < 2; mt++) {
                    c[mt][ntl][0] = b0v; c[mt][ntl][1] = b1v;
                    c[mt][ntl][2] = b0v; c[mt][ntl][3] = b1v;
                }
            }

            // depth-2 rotating prefetch of B-frags from L2
            uint2 bb[3][4];
            #pragma unroll
            for (int p = 0; p < 2; p++)
                #pragma unroll
                for (int ntl = 0; ntl < 4; ntl++)
                    bb[p][ntl] = __ldg(&g_Wp[(p * 64 + 4 * warp + ntl) * 32 + lane]);
            #pragma unroll
            for (int kt = 0; kt < 16; kt++) {
                const int cur = kt % 3;
                if (kt < 14) {
                    const int nxt = (kt + 2) % 3;
                    #pragma unroll
                    for (int ntl = 0; ntl < 4; ntl++)
                        bb[nxt][ntl] =
                            __ldg(&g_Wp[((kt + 2) * 64 + 4 * warp + ntl) * 32 + lane]);
                }
                uint4 A0 = af_ld(S.AF, kt, 0, lane);
                uint4 A1 = af_ld(S.AF, kt, 1, lane);
                #pragma unroll
                for (int ntl = 0; ntl < 4; ntl++) {
                    mma4(c[0][ntl], A0, bb[cur][ntl]);
                    mma4(c[1][ntl], A1, bb[cur][ntl]);
                }
            }
            __syncthreads();   // all AF reads done before staging overwrites

            // LSTM epilogue: lane-pair exchange -> full i,f,g,o per lane
            const bool odd = (q & 1);
            #pragma unroll
            for (int mt = 0; mt < 2; mt++) {
                #pragma unroll
                for (int ntl = 0; ntl < 4; ntl++) {
                    float e0 = __shfl_xor_sync(0xffffffffu, c[mt][ntl][0], 1);
                    float e1 = __shfl_xor_sync(0xffffffffu, c[mt][ntl][1], 1);
                    float e2 = __shfl_xor_sync(0xffffffffu, c[mt][ntl][2], 1);
                    float e3 = __shfl_xor_sync(0xffffffffu, c[mt][ntl][3], 1);
                    float iv, fv, gv, ov;
                    int row = 16 * mt + gr + (odd ? 8 : 0);
                    if (!odd) { iv = c[mt][ntl][0]; fv = c[mt][ntl][1]; gv = e0; ov = e1; }
                    else      { iv = e2; fv = e3; gv = c[mt][ntl][2]; ov = c[mt][ntl][3]; }
                    int hu = 8 * warp + 2 * ntl + (q >> 1);
                    float co = S.Cst[hu][row];
                    float cn = sigf(fv) * co + sigf(iv) * tanhf_(gv);
                    float hn = sigf(ov) * tanhf_(cn);
                    S.Cst[hu][row] = cn;
                    S.Hs[hu][row] = hn;
                }
            }

            // stage next-step inputs -> scalars + AF(M,D,GX)
            if (havenext) {
                #pragma unroll
                for (int j = 0; j < 2; j++) {
                    int row = warp + 16 * j;
                    int f0 = 2 * lane;
                    S.Xv[f0][row] = nx[j].x;  S.Xv[f0 + 1][row] = nx[j].y;
                    S.Ms[f0][row] = nm[j].x;  S.Ms[f0 + 1][row] = nm[j].y;
                    af_storep(S.AF, KT_M, f0, row, nm[j].x, nm[j].y);
                    af_storep(S.AF, KT_D, f0, row, nd[j].x, nd[j].y);
                    float g0 = __expf(-fmaxf(nd[j].x * S.wdx[f0]     + S.bdx[f0],     0.f));
                    float g1 = __expf(-fmaxf(nd[j].y * S.wdx[f0 + 1] + S.bdx[f0 + 1], 0.f));
                    af_storep(S.AF, KT_GX, f0, row, g0, g1);
                }
            }
        }
        __syncthreads();
    }

    // ---- loss block-reduce (deterministic per block) ----
    float v = loss_acc;
    #pragma unroll
    for (int o = 16; o; o >>= 1) v += __shfl_down_sync(0xffffffffu, v, o);
    if (lane == 0) S.red[warp] = v;
    __syncthreads();
    if (tid == 0) {
        float s = 0.f;
        for (int w = 0; w < 16; w++) s += S.red[w];
        g_losspart[blockIdx.x] = s;
    }

    // ---- predictions ----
    if (tid < RPB) {
        float p = S.bo0;
        #pragma unroll 4
        for (int u = 0; u < 128; u++) p += S.Hs[u][tid] * S.wos[u];
        out[1 + IMP_N + row0 + tid] = p;
    }
}

extern "C" void kernel_launch(void* const* d_in, const int* in_sizes, int n_in,
                              void* d_out, int out_size) {
    const float* values = (const float*)d_in[0];
    const float* masks  = (const float*)d_in[1];
    const float* deltas = (const float*)d_in[2];
    const float* Wdh = (const float*)d_in[3];
    const float* bdh = (const float*)d_in[4];
    const float* Wdx = (const float*)d_in[5];
    const float* bdx = (const float*)d_in[6];
    const float* Wh  = (const float*)d_in[7];
    const float* bh  = (const float*)d_in[8];
    const float* Wf  = (const float*)d_in[9];
    const float* bf  = (const float*)d_in[10];
    const float* Wc  = (const float*)d_in[11];
    const float* bc  = (const float*)d_in[12];
    const float* W_ih = (const float*)d_in[13];
    const float* W_hh = (const float*)d_in[14];
    const float* b_ih = (const float*)d_in[15];
    const float* b_hh = (const float*)d_in[16];
    const float* Wo  = (const float*)d_in[17];
    const float* bo  = (const float*)d_in[18];
    float* out = (float*)d_out;

    cudaFuncSetAttribute(brits_main, cudaFuncAttributeMaxDynamicSharedMemorySize,
                         (int)sizeof(SM));

    k_denom<<<TT, 256>>>(masks);
    k_prepw<<<128, 256>>>(W_ih, W_hh, b_ih, b_hh);
    brits_main<<<NBLK, NTH, sizeof(SM)>>>(values, masks, deltas,
                                          Wdh, bdh, Wdx, bdx, Wh, bh, Wf, bf,
                                          Wc, bc, Wo, bo, out);
    k_fin<<<1, 32>>>(out);
}